// round 1
// baseline (speedup 1.0000x reference)
#include <cuda_runtime.h>
#include <math.h>

#define S_  1024
#define B_  8
#define D_  1024
#define H_  16
#define HD_ 64
#define F_  4096
#define E_  8
#define NTOK (S_ * B_)      // 8192 tokens
#define D3_ (3 * D_)        // 3072

// ---------------- scratch (device globals: no allocs allowed) ----------------
__device__ float g_qkv [(size_t)NTOK * D3_];   // 96 MB
__device__ float g_attn[(size_t)NTOK * D_];    // 32 MB
__device__ float g_proj[(size_t)NTOK * D_];    // 32 MB
__device__ float g_x1  [(size_t)NTOK * D_];    // 32 MB
__device__ float g_h   [(size_t)NTOK * F_];    // 128 MB
__device__ float g_moe [(size_t)NTOK * D_];    // 32 MB

// ---------------------------------------------------------------------------
// Generic fp32 GEMM:  C[M,N] = A[M,K] @ B[N,K]^T + bias[N]   (optional ReLU)
// A row-major with leading dim lda, B row-major with leading dim ldb.
// 128x128 tile, BK=16, 256 threads, 8x8 micro-tile per thread.
// ---------------------------------------------------------------------------
template<bool RELU>
__global__ void __launch_bounds__(256, 2)
gemm_tn(const float* __restrict__ A, int lda,
        const float* __restrict__ Bm, int ldb,
        const float* __restrict__ bias,
        float* __restrict__ C, int ldc,
        int M, int N, int K)
{
    __shared__ float As[16][129];
    __shared__ float Bs[16][129];
    const int tid = threadIdx.x;
    const int tx = tid & 15, ty = tid >> 4;
    const int m0 = blockIdx.y * 128;
    const int n0 = blockIdx.x * 128;

    float acc[8][8];
#pragma unroll
    for (int i = 0; i < 8; i++)
#pragma unroll
        for (int j = 0; j < 8; j++) acc[i][j] = 0.f;

    for (int k0 = 0; k0 < K; k0 += 16) {
#pragma unroll
        for (int t = 0; t < 2; t++) {
            int f   = tid + t * 256;
            int row = f >> 2;          // 0..127
            int kq  = (f & 3) << 2;    // 0,4,8,12
            float4 va = make_float4(0.f, 0.f, 0.f, 0.f);
            if (m0 + row < M)
                va = *(const float4*)(A + (size_t)(m0 + row) * lda + k0 + kq);
            As[kq + 0][row] = va.x; As[kq + 1][row] = va.y;
            As[kq + 2][row] = va.z; As[kq + 3][row] = va.w;
            float4 vb = make_float4(0.f, 0.f, 0.f, 0.f);
            if (n0 + row < N)
                vb = *(const float4*)(Bm + (size_t)(n0 + row) * ldb + k0 + kq);
            Bs[kq + 0][row] = vb.x; Bs[kq + 1][row] = vb.y;
            Bs[kq + 2][row] = vb.z; Bs[kq + 3][row] = vb.w;
        }
        __syncthreads();
#pragma unroll
        for (int k = 0; k < 16; k++) {
            float a[8], b[8];
#pragma unroll
            for (int i = 0; i < 8; i++) a[i] = As[k][ty + i * 16];
#pragma unroll
            for (int j = 0; j < 8; j++) b[j] = Bs[k][tx + j * 16];
#pragma unroll
            for (int i = 0; i < 8; i++)
#pragma unroll
                for (int j = 0; j < 8; j++)
                    acc[i][j] += a[i] * b[j];
        }
        __syncthreads();
    }

    float bv[8];
#pragma unroll
    for (int j = 0; j < 8; j++) {
        int c = n0 + tx + j * 16;
        bv[j] = (c < N) ? bias[c] : 0.f;
    }
#pragma unroll
    for (int i = 0; i < 8; i++) {
        int r = m0 + ty + i * 16;
        if (r < M) {
#pragma unroll
            for (int j = 0; j < 8; j++) {
                int c = n0 + tx + j * 16;
                if (c < N) {
                    float v = acc[i][j] + bv[j];
                    if (RELU) v = fmaxf(v, 0.f);
                    C[(size_t)r * ldc + c] = v;
                }
            }
        }
    }
}

// ---------------------------------------------------------------------------
// Flash attention (fp32): one CTA = one (b,h) head and a 64-query tile.
// K/V streamed in 32-key tiles with online softmax. q pre-scaled by 1/8.
// qkv layout: token t = s*B_+b, row of 3072: [q(1024) | k(1024) | v(1024)],
// head slice h*64..h*64+63.
// ---------------------------------------------------------------------------
__global__ void __launch_bounds__(256)
attn_flash(const float* __restrict__ qkv, float* __restrict__ out)
{
    const int s0 = blockIdx.x * 64;
    const int bh = blockIdx.y;
    const int b  = bh / H_;
    const int h  = bh % H_;

    __shared__ float Qs[64 * 64];    // [m][d]
    __shared__ float KPs[64 * 33];   // K: [d][n] (stride 33); reused as P: [r][t] (stride 33)
    __shared__ float Vs[32 * 64];    // [t][d]

    const int tid = threadIdx.x;
    const int tx = tid & 15, ty = tid >> 4;

    for (int idx = tid; idx < 64 * 64; idx += 256) {
        int m = idx >> 6, d = idx & 63;
        Qs[m * 64 + d] =
            qkv[((size_t)(s0 + m) * B_ + b) * D3_ + h * HD_ + d] * 0.125f;
    }

    float mrun[4], lrun[4], oacc[4][4];
#pragma unroll
    for (int i = 0; i < 4; i++) {
        mrun[i] = -1e30f;
        lrun[i] = 0.f;
#pragma unroll
        for (int j = 0; j < 4; j++) oacc[i][j] = 0.f;
    }
    __syncthreads();

    for (int t0 = 0; t0 < S_; t0 += 32) {
        for (int idx = tid; idx < 32 * 64; idx += 256) {
            int n = idx >> 6, d = idx & 63;
            size_t base = ((size_t)(t0 + n) * B_ + b) * D3_ + h * HD_ + d;
            KPs[d * 33 + n] = qkv[base + D_];
            Vs[n * 64 + d]  = qkv[base + 2 * D_];
        }
        __syncthreads();

        // S = Q K^T  (rows ty+i*16, key cols tx and tx+16)
        float sc[4][2];
#pragma unroll
        for (int i = 0; i < 4; i++) { sc[i][0] = 0.f; sc[i][1] = 0.f; }
        for (int d = 0; d < 64; d++) {
            float a[4], bb0, bb1;
#pragma unroll
            for (int i = 0; i < 4; i++) a[i] = Qs[(ty + i * 16) * 64 + d];
            bb0 = KPs[d * 33 + tx];
            bb1 = KPs[d * 33 + tx + 16];
#pragma unroll
            for (int i = 0; i < 4; i++) {
                sc[i][0] += a[i] * bb0;
                sc[i][1] += a[i] * bb1;
            }
        }
        __syncthreads();   // everyone done reading K before P overwrites it

        // online softmax (row owned by 16 lanes sharing ty; xor<16 stays in group)
#pragma unroll
        for (int i = 0; i < 4; i++) {
            float rmax = fmaxf(sc[i][0], sc[i][1]);
#pragma unroll
            for (int o = 8; o > 0; o >>= 1)
                rmax = fmaxf(rmax, __shfl_xor_sync(0xffffffffu, rmax, o));
            float mn   = fmaxf(mrun[i], rmax);
            float corr = __expf(mrun[i] - mn);
            mrun[i] = mn;
            float p0 = __expf(sc[i][0] - mn);
            float p1 = __expf(sc[i][1] - mn);
            float rsum = p0 + p1;
#pragma unroll
            for (int o = 8; o > 0; o >>= 1)
                rsum += __shfl_xor_sync(0xffffffffu, rsum, o);
            lrun[i] = lrun[i] * corr + rsum;
#pragma unroll
            for (int j = 0; j < 4; j++) oacc[i][j] *= corr;
            KPs[(ty + i * 16) * 33 + tx]      = p0;
            KPs[(ty + i * 16) * 33 + tx + 16] = p1;
        }
        __syncthreads();

        // O += P V
        for (int t = 0; t < 32; t++) {
            float a[4], bb[4];
#pragma unroll
            for (int i = 0; i < 4; i++) a[i] = KPs[(ty + i * 16) * 33 + t];
#pragma unroll
            for (int j = 0; j < 4; j++) bb[j] = Vs[t * 64 + tx + j * 16];
#pragma unroll
            for (int i = 0; i < 4; i++)
#pragma unroll
                for (int j = 0; j < 4; j++) oacc[i][j] += a[i] * bb[j];
        }
        __syncthreads();
    }

#pragma unroll
    for (int i = 0; i < 4; i++) {
        int r = s0 + ty + i * 16;
        float inv = 1.f / lrun[i];
#pragma unroll
        for (int j = 0; j < 4; j++) {
            int c = tx + j * 16;
            out[((size_t)r * B_ + b) * D_ + h * HD_ + c] = oacc[i][j] * inv;
        }
    }
}

// ---------------------------------------------------------------------------
// out = LayerNorm(a + r) * gamma + beta   — one CTA per token row (D=1024).
// ---------------------------------------------------------------------------
__global__ void __launch_bounds__(256)
add_ln_kernel(const float* __restrict__ a, const float* __restrict__ r,
              const float* __restrict__ gamma, const float* __restrict__ beta,
              float* __restrict__ out)
{
    const int row = blockIdx.x;
    __shared__ float buf[D_];
    __shared__ float ws[8], wq[8];
    __shared__ float red[2];
    const int tid = threadIdx.x;
    const size_t base = (size_t)row * D_;

    float s = 0.f, sq = 0.f;
    for (int i = tid; i < D_; i += 256) {
        float v = a[base + i] + r[base + i];
        buf[i] = v;
        s += v;
        sq += v * v;
    }
#pragma unroll
    for (int o = 16; o > 0; o >>= 1) {
        s  += __shfl_xor_sync(0xffffffffu, s, o);
        sq += __shfl_xor_sync(0xffffffffu, sq, o);
    }
    int lane = tid & 31, wid = tid >> 5;
    if (lane == 0) { ws[wid] = s; wq[wid] = sq; }
    __syncthreads();
    if (tid == 0) {
        float S = 0.f, Q = 0.f;
#pragma unroll
        for (int w = 0; w < 8; w++) { S += ws[w]; Q += wq[w]; }
        float mu  = S * (1.0f / D_);
        float var = Q * (1.0f / D_) - mu * mu;
        red[0] = mu;
        red[1] = rsqrtf(var + 1e-5f);
    }
    __syncthreads();
    float mu = red[0], rstd = red[1];
    for (int i = tid; i < D_; i += 256)
        out[base + i] = (buf[i] - mu) * rstd * gamma[i] + beta[i];
}

// ---------------------------------------------------------------------------
extern "C" void kernel_launch(void* const* d_in, const int* in_sizes, int n_in,
                              void* d_out, int out_size)
{
    (void)in_sizes; (void)n_in; (void)out_size;
    const float* src  = (const float*)d_in[0];
    const float* inw  = (const float*)d_in[1];
    const float* inb  = (const float*)d_in[2];
    const float* outw = (const float*)d_in[3];
    const float* outb = (const float*)d_in[4];
    const float* g1   = (const float*)d_in[5];
    const float* be1  = (const float*)d_in[6];
    const float* g2   = (const float*)d_in[7];
    const float* be2  = (const float*)d_in[8];
    const float* w1   = (const float*)d_in[9];
    const float* b1   = (const float*)d_in[10];
    const float* w2   = (const float*)d_in[11];
    const float* b2   = (const float*)d_in[12];
    float* out = (float*)d_out;

    float *qkv, *attn, *proj, *x1, *hbuf, *moe;
    cudaGetSymbolAddress((void**)&qkv,  g_qkv);
    cudaGetSymbolAddress((void**)&attn, g_attn);
    cudaGetSymbolAddress((void**)&proj, g_proj);
    cudaGetSymbolAddress((void**)&x1,   g_x1);
    cudaGetSymbolAddress((void**)&hbuf, g_h);
    cudaGetSymbolAddress((void**)&moe,  g_moe);

    dim3 blk(256);

    // 1) qkv = src @ in_proj_w^T + in_proj_b      [8192 x 3072]
    gemm_tn<false><<<dim3(D3_ / 128, NTOK / 128), blk>>>(
        src, D_, inw, D_, inb, qkv, D3_, NTOK, D3_, D_);

    // 2) attention -> attn [8192 x 1024]
    attn_flash<<<dim3(S_ / 64, B_ * H_), blk>>>(qkv, attn);

    // 3) proj = attn @ out_proj_w^T + out_proj_b [8192 x 1024]
    gemm_tn<false><<<dim3(D_ / 128, NTOK / 128), blk>>>(
        attn, D_, outw, D_, outb, proj, D_, NTOK, D_, D_);

    // 4) x1 = LN(src + proj)
    add_ln_kernel<<<NTOK, blk>>>(src, proj, g1, be1, x1);

    // 5) MoE: contiguous token splits, per-expert GEMM pairs
    const int splits[E_] = {6852, 857, 254, 107, 55, 32, 20, 15};
    int off = 0;
    for (int e = 0; e < E_; e++) {
        int n  = splits[e];
        int mt = (n + 127) / 128;
        gemm_tn<true><<<dim3(F_ / 128, mt), blk>>>(
            x1 + (size_t)off * D_, D_,
            w1 + (size_t)e * F_ * D_, D_,
            b1 + (size_t)e * F_,
            hbuf + (size_t)off * F_, F_, n, F_, D_);
        gemm_tn<false><<<dim3(D_ / 128, mt), blk>>>(
            hbuf + (size_t)off * F_, F_,
            w2 + (size_t)e * D_ * F_, F_,
            b2 + (size_t)e * D_,
            moe + (size_t)off * D_, D_, n, D_, F_);
        off += n;
    }

    // 6) out = LN(x1 + moe)
    add_ln_kernel<<<NTOK, blk>>>(x1, moe, g2, be2, out);
}

// round 2
// speedup vs baseline: 1.2317x; 1.2317x over previous
#include <cuda_runtime.h>
#include <mma.h>
#include <math.h>

using namespace nvcuda;

#define S_  1024
#define B_  8
#define D_  1024
#define H_  16
#define HD_ 64
#define F_  4096
#define E_  8
#define NTOK (S_ * B_)      // 8192 tokens
#define D3_ (3 * D_)        // 3072

// ---------------- scratch (device globals: no allocs allowed) ----------------
__device__ float g_qkv [(size_t)NTOK * D3_];   // 96 MB
__device__ float g_attn[(size_t)NTOK * D_];    // 32 MB
__device__ float g_proj[(size_t)NTOK * D_];    // 32 MB
__device__ float g_x1  [(size_t)NTOK * D_];    // 32 MB
__device__ float g_h   [(size_t)NTOK * F_];    // 128 MB
__device__ float g_moe [(size_t)NTOK * D_];    // 32 MB

// ---------------------------------------------------------------------------
// tf32 WMMA GEMM: C[M,N] = A[M,K] @ B[N,K]^T + bias[N]  (optional ReLU)
// A row-major (lda), B row-major (ldb) — both K-contiguous.
// Block tile 128x128, BK=32, 256 threads = 8 warps, warp tile 32x64
// (2x4 wmma m16n16k8 fragments). fp32 accumulation.
// ---------------------------------------------------------------------------
#define BK 32
#define ASTRIDE 36

template<bool RELU>
__global__ void __launch_bounds__(256)
gemm_tf32(const float* __restrict__ A, int lda,
          const float* __restrict__ Bm, int ldb,
          const float* __restrict__ bias,
          float* __restrict__ C, int ldc,
          int M, int N, int K)
{
    __shared__ float As[128][ASTRIDE];
    __shared__ float Bs[128][ASTRIDE];
    __shared__ float stage[8][256];

    const int tid  = threadIdx.x;
    const int warp = tid >> 5;
    const int lane = tid & 31;
    const int wm   = warp & 3;    // warp row  (4 warps over M)
    const int wn   = warp >> 2;   // warp col  (2 warps over N)
    const int m0 = blockIdx.y * 128;
    const int n0 = blockIdx.x * 128;

    wmma::fragment<wmma::accumulator, 16, 16, 8, float> acc[2][4];
#pragma unroll
    for (int i = 0; i < 2; i++)
#pragma unroll
        for (int j = 0; j < 4; j++)
            wmma::fill_fragment(acc[i][j], 0.0f);

    for (int k0 = 0; k0 < K; k0 += BK) {
        // cooperative load: 128 rows x 32 cols each for A and B (float4)
#pragma unroll
        for (int t = 0; t < 4; t++) {
            int f   = tid + t * 256;
            int row = f >> 3;           // 0..127
            int c4  = (f & 7) << 2;     // 0,4,...,28
            float4 va = make_float4(0.f, 0.f, 0.f, 0.f);
            if (m0 + row < M)
                va = *(const float4*)(A + (size_t)(m0 + row) * lda + k0 + c4);
            As[row][c4 + 0] = va.x; As[row][c4 + 1] = va.y;
            As[row][c4 + 2] = va.z; As[row][c4 + 3] = va.w;
            float4 vb = make_float4(0.f, 0.f, 0.f, 0.f);
            if (n0 + row < N)
                vb = *(const float4*)(Bm + (size_t)(n0 + row) * ldb + k0 + c4);
            Bs[row][c4 + 0] = vb.x; Bs[row][c4 + 1] = vb.y;
            Bs[row][c4 + 2] = vb.z; Bs[row][c4 + 3] = vb.w;
        }
        __syncthreads();

#pragma unroll
        for (int kk = 0; kk < BK; kk += 8) {
            wmma::fragment<wmma::matrix_a, 16, 16, 8, wmma::precision::tf32,
                           wmma::row_major> af[2];
            wmma::fragment<wmma::matrix_b, 16, 16, 8, wmma::precision::tf32,
                           wmma::col_major> bf[4];
#pragma unroll
            for (int i = 0; i < 2; i++) {
                wmma::load_matrix_sync(af[i], &As[wm * 32 + i * 16][kk], ASTRIDE);
#pragma unroll
                for (int e = 0; e < af[i].num_elements; e++)
                    af[i].x[e] = wmma::__float_to_tf32(af[i].x[e]);
            }
#pragma unroll
            for (int j = 0; j < 4; j++) {
                wmma::load_matrix_sync(bf[j], &Bs[wn * 64 + j * 16][kk], ASTRIDE);
#pragma unroll
                for (int e = 0; e < bf[j].num_elements; e++)
                    bf[j].x[e] = wmma::__float_to_tf32(bf[j].x[e]);
            }
#pragma unroll
            for (int i = 0; i < 2; i++)
#pragma unroll
                for (int j = 0; j < 4; j++)
                    wmma::mma_sync(acc[i][j], af[i], bf[j], acc[i][j]);
        }
        __syncthreads();
    }

    // epilogue: stage each 16x16 fragment through smem, add bias (+ReLU), guard
#pragma unroll
    for (int i = 0; i < 2; i++) {
#pragma unroll
        for (int j = 0; j < 4; j++) {
            wmma::store_matrix_sync(&stage[warp][0], acc[i][j], 16,
                                    wmma::mem_row_major);
            __syncwarp();
            int r0 = m0 + wm * 32 + i * 16;
            int c0 = n0 + wn * 64 + j * 16;
#pragma unroll
            for (int q = 0; q < 8; q++) {
                int idx = lane + q * 32;
                int r = idx >> 4, c = idx & 15;
                if (r0 + r < M && c0 + c < N) {
                    float v = stage[warp][idx] + bias[c0 + c];
                    if (RELU) v = fmaxf(v, 0.f);
                    C[(size_t)(r0 + r) * ldc + c0 + c] = v;
                }
            }
            __syncwarp();
        }
    }
}

// ---------------------------------------------------------------------------
// Flash attention (fp32): one CTA = one (b,h) head and a 64-query tile.
// ---------------------------------------------------------------------------
__global__ void __launch_bounds__(256)
attn_flash(const float* __restrict__ qkv, float* __restrict__ out)
{
    const int s0 = blockIdx.x * 64;
    const int bh = blockIdx.y;
    const int b  = bh / H_;
    const int h  = bh % H_;

    __shared__ float Qs[64 * 64];
    __shared__ float KPs[64 * 33];
    __shared__ float Vs[32 * 64];

    const int tid = threadIdx.x;
    const int tx = tid & 15, ty = tid >> 4;

    for (int idx = tid; idx < 64 * 64; idx += 256) {
        int m = idx >> 6, d = idx & 63;
        Qs[m * 64 + d] =
            qkv[((size_t)(s0 + m) * B_ + b) * D3_ + h * HD_ + d] * 0.125f;
    }

    float mrun[4], lrun[4], oacc[4][4];
#pragma unroll
    for (int i = 0; i < 4; i++) {
        mrun[i] = -1e30f;
        lrun[i] = 0.f;
#pragma unroll
        for (int j = 0; j < 4; j++) oacc[i][j] = 0.f;
    }
    __syncthreads();

    for (int t0 = 0; t0 < S_; t0 += 32) {
        for (int idx = tid; idx < 32 * 64; idx += 256) {
            int n = idx >> 6, d = idx & 63;
            size_t base = ((size_t)(t0 + n) * B_ + b) * D3_ + h * HD_ + d;
            KPs[d * 33 + n] = qkv[base + D_];
            Vs[n * 64 + d]  = qkv[base + 2 * D_];
        }
        __syncthreads();

        float sc[4][2];
#pragma unroll
        for (int i = 0; i < 4; i++) { sc[i][0] = 0.f; sc[i][1] = 0.f; }
        for (int d = 0; d < 64; d++) {
            float a[4], bb0, bb1;
#pragma unroll
            for (int i = 0; i < 4; i++) a[i] = Qs[(ty + i * 16) * 64 + d];
            bb0 = KPs[d * 33 + tx];
            bb1 = KPs[d * 33 + tx + 16];
#pragma unroll
            for (int i = 0; i < 4; i++) {
                sc[i][0] += a[i] * bb0;
                sc[i][1] += a[i] * bb1;
            }
        }
        __syncthreads();

#pragma unroll
        for (int i = 0; i < 4; i++) {
            float rmax = fmaxf(sc[i][0], sc[i][1]);
#pragma unroll
            for (int o = 8; o > 0; o >>= 1)
                rmax = fmaxf(rmax, __shfl_xor_sync(0xffffffffu, rmax, o));
            float mn   = fmaxf(mrun[i], rmax);
            float corr = __expf(mrun[i] - mn);
            mrun[i] = mn;
            float p0 = __expf(sc[i][0] - mn);
            float p1 = __expf(sc[i][1] - mn);
            float rsum = p0 + p1;
#pragma unroll
            for (int o = 8; o > 0; o >>= 1)
                rsum += __shfl_xor_sync(0xffffffffu, rsum, o);
            lrun[i] = lrun[i] * corr + rsum;
#pragma unroll
            for (int j = 0; j < 4; j++) oacc[i][j] *= corr;
            KPs[(ty + i * 16) * 33 + tx]      = p0;
            KPs[(ty + i * 16) * 33 + tx + 16] = p1;
        }
        __syncthreads();

        for (int t = 0; t < 32; t++) {
            float a[4], bb[4];
#pragma unroll
            for (int i = 0; i < 4; i++) a[i] = KPs[(ty + i * 16) * 33 + t];
#pragma unroll
            for (int j = 0; j < 4; j++) bb[j] = Vs[t * 64 + tx + j * 16];
#pragma unroll
            for (int i = 0; i < 4; i++)
#pragma unroll
                for (int j = 0; j < 4; j++) oacc[i][j] += a[i] * bb[j];
        }
        __syncthreads();
    }

#pragma unroll
    for (int i = 0; i < 4; i++) {
        int r = s0 + ty + i * 16;
        float inv = 1.f / lrun[i];
#pragma unroll
        for (int j = 0; j < 4; j++) {
            int c = tx + j * 16;
            out[((size_t)r * B_ + b) * D_ + h * HD_ + c] = oacc[i][j] * inv;
        }
    }
}

// ---------------------------------------------------------------------------
// out = LayerNorm(a + r) * gamma + beta
// ---------------------------------------------------------------------------
__global__ void __launch_bounds__(256)
add_ln_kernel(const float* __restrict__ a, const float* __restrict__ r,
              const float* __restrict__ gamma, const float* __restrict__ beta,
              float* __restrict__ out)
{
    const int row = blockIdx.x;
    __shared__ float buf[D_];
    __shared__ float ws[8], wq[8];
    __shared__ float red[2];
    const int tid = threadIdx.x;
    const size_t base = (size_t)row * D_;

    float s = 0.f, sq = 0.f;
    for (int i = tid; i < D_; i += 256) {
        float v = a[base + i] + r[base + i];
        buf[i] = v;
        s += v;
        sq += v * v;
    }
#pragma unroll
    for (int o = 16; o > 0; o >>= 1) {
        s  += __shfl_xor_sync(0xffffffffu, s, o);
        sq += __shfl_xor_sync(0xffffffffu, sq, o);
    }
    int lane = tid & 31, wid = tid >> 5;
    if (lane == 0) { ws[wid] = s; wq[wid] = sq; }
    __syncthreads();
    if (tid == 0) {
        float S = 0.f, Q = 0.f;
#pragma unroll
        for (int w = 0; w < 8; w++) { S += ws[w]; Q += wq[w]; }
        float mu  = S * (1.0f / D_);
        float var = Q * (1.0f / D_) - mu * mu;
        red[0] = mu;
        red[1] = rsqrtf(var + 1e-5f);
    }
    __syncthreads();
    float mu = red[0], rstd = red[1];
    for (int i = tid; i < D_; i += 256)
        out[base + i] = (buf[i] - mu) * rstd * gamma[i] + beta[i];
}

// ---------------------------------------------------------------------------
extern "C" void kernel_launch(void* const* d_in, const int* in_sizes, int n_in,
                              void* d_out, int out_size)
{
    (void)in_sizes; (void)n_in; (void)out_size;
    const float* src  = (const float*)d_in[0];
    const float* inw  = (const float*)d_in[1];
    const float* inb  = (const float*)d_in[2];
    const float* outw = (const float*)d_in[3];
    const float* outb = (const float*)d_in[4];
    const float* g1   = (const float*)d_in[5];
    const float* be1  = (const float*)d_in[6];
    const float* g2   = (const float*)d_in[7];
    const float* be2  = (const float*)d_in[8];
    const float* w1   = (const float*)d_in[9];
    const float* b1   = (const float*)d_in[10];
    const float* w2   = (const float*)d_in[11];
    const float* b2   = (const float*)d_in[12];
    float* out = (float*)d_out;

    float *qkv, *attn, *proj, *x1, *hbuf, *moe;
    cudaGetSymbolAddress((void**)&qkv,  g_qkv);
    cudaGetSymbolAddress((void**)&attn, g_attn);
    cudaGetSymbolAddress((void**)&proj, g_proj);
    cudaGetSymbolAddress((void**)&x1,   g_x1);
    cudaGetSymbolAddress((void**)&hbuf, g_h);
    cudaGetSymbolAddress((void**)&moe,  g_moe);

    dim3 blk(256);

    // 1) qkv = src @ in_proj_w^T + in_proj_b      [8192 x 3072]
    gemm_tf32<false><<<dim3(D3_ / 128, NTOK / 128), blk>>>(
        src, D_, inw, D_, inb, qkv, D3_, NTOK, D3_, D_);

    // 2) attention -> attn [8192 x 1024]
    attn_flash<<<dim3(S_ / 64, B_ * H_), blk>>>(qkv, attn);

    // 3) proj = attn @ out_proj_w^T + out_proj_b [8192 x 1024]
    gemm_tf32<false><<<dim3(D_ / 128, NTOK / 128), blk>>>(
        attn, D_, outw, D_, outb, proj, D_, NTOK, D_, D_);

    // 4) x1 = LN(src + proj)
    add_ln_kernel<<<NTOK, blk>>>(src, proj, g1, be1, x1);

    // 5) MoE: contiguous token splits, per-expert GEMM pairs
    const int splits[E_] = {6852, 857, 254, 107, 55, 32, 20, 15};
    int off = 0;
    for (int e = 0; e < E_; e++) {
        int n  = splits[e];
        int mt = (n + 127) / 128;
        gemm_tf32<true><<<dim3(F_ / 128, mt), blk>>>(
            x1 + (size_t)off * D_, D_,
            w1 + (size_t)e * F_ * D_, D_,
            b1 + (size_t)e * F_,
            hbuf + (size_t)off * F_, F_, n, F_, D_);
        gemm_tf32<false><<<dim3(D_ / 128, mt), blk>>>(
            hbuf + (size_t)off * F_, F_,
            w2 + (size_t)e * D_ * F_, F_,
            b2 + (size_t)e * D_,
            moe + (size_t)off * D_, D_, n, D_, F_);
        off += n;
    }

    // 6) out = LN(x1 + moe)
    add_ln_kernel<<<NTOK, blk>>>(x1, moe, g2, be2, out);
}

// round 4
// speedup vs baseline: 2.6090x; 2.1183x over previous
#include <cuda_runtime.h>
#include <mma.h>
#include <math.h>
#include <cstdint>

using namespace nvcuda;

#define S_  1024
#define B_  8
#define D_  1024
#define H_  16
#define HD_ 64
#define F_  4096
#define E_  8
#define NTOK (S_ * B_)      // 8192 tokens
#define D3_ (3 * D_)        // 3072

// ---------------- scratch (device globals: no allocs allowed) ----------------
__device__ float g_qkv [(size_t)NTOK * D3_];   // 96 MB
__device__ float g_attn[(size_t)NTOK * D_];    // 32 MB
__device__ float g_proj[(size_t)NTOK * D_];    // 32 MB
__device__ float g_x1  [(size_t)NTOK * D_];    // 32 MB
__device__ float g_h   [(size_t)NTOK * F_];    // 128 MB
__device__ float g_moe [(size_t)NTOK * D_];    // 32 MB

// ---------------------------------------------------------------------------
// cp.async helpers
// ---------------------------------------------------------------------------
__device__ __forceinline__ void cp_async16(unsigned int smem_addr,
                                           const void* gptr, bool valid)
{
    int sz = valid ? 16 : 0;
    asm volatile("cp.async.cg.shared.global [%0], [%1], 16, %2;\n"
                 :: "r"(smem_addr), "l"(gptr), "r"(sz));
}
__device__ __forceinline__ void cp_commit() {
    asm volatile("cp.async.commit_group;\n");
}
__device__ __forceinline__ void cp_wait1() {
    asm volatile("cp.async.wait_group 1;\n");
}

// ---------------------------------------------------------------------------
// tf32 WMMA GEMM with 2-stage cp.async pipeline.
//   C[M,N] = A[M,K] @ W[N,K]^T + bias[N]   (optional ReLU)
// MOE mode: blockIdx.y is a global M-tile index mapped onto 8 experts with
// contiguous token ranges; weight/bias advance by per-expert strides.
// Block tile 128x128, BK=16, 256 threads = 8 warps, warp tile 32x64.
// No explicit float->tf32 conversion: HMMA truncates mantissa in HW.
// ---------------------------------------------------------------------------
#define BK  16
#define AST 20   // smem row stride (16 + 4 pad)

template<bool RELU, bool MOE>
__global__ void __launch_bounds__(256, 2)
gemm_tf32(const float* __restrict__ Abase, int lda,
          const float* __restrict__ Wbase, int ldb,
          const float* __restrict__ biasbase,
          float* __restrict__ C, int ldc,
          int M, int N, int K,
          size_t wstride, int bstride)
{
    __shared__ float As[2][128][AST];
    __shared__ float Bs[2][128][AST];

    const int tid  = threadIdx.x;
    const int warp = tid >> 5;
    const int lane = tid & 31;
    const int wm   = warp & 3;
    const int wn   = warp >> 2;
    const int n0   = blockIdx.x * 128;

    // resolve M tile (plain or MoE expert mapping)
    int m0, Mb;
    const float* A = Abase;
    const float* W = Wbase;
    const float* bias = biasbase;
    if (MOE) {
        const int tcnt[8] = {54, 7, 2, 1, 1, 1, 1, 1};
        const int toff[8] = {0, 6852, 7709, 7963, 8070, 8125, 8157, 8177};
        const int tn[8]   = {6852, 857, 254, 107, 55, 32, 20, 15};
        int y = blockIdx.y, e = 0, acc = 0;
        while (y >= acc + tcnt[e]) { acc += tcnt[e]; e++; }
        m0 = toff[e] + (y - acc) * 128;
        Mb = toff[e] + tn[e];
        W    = Wbase + (size_t)e * wstride;
        bias = biasbase + (size_t)e * bstride;
    } else {
        m0 = blockIdx.y * 128;
        Mb = M;
    }

    // per-thread load slots: 2 rows of A and 2 rows of B per stage (float4)
    const int lrow = tid >> 2;           // 0..63
    const int lcol = (tid & 3) << 2;     // 0,4,8,12

    unsigned int sA = (unsigned int)__cvta_generic_to_shared(&As[0][0][0]);
    unsigned int sB = (unsigned int)__cvta_generic_to_shared(&Bs[0][0][0]);
    const unsigned int stageBytes = 128 * AST * 4;

    auto issue = [&](int stage, int k0) {
#pragma unroll
        for (int t = 0; t < 2; t++) {
            int row = lrow + t * 64;
            bool va = (m0 + row < Mb);
            cp_async16(sA + stage * stageBytes + (row * AST + lcol) * 4,
                       A + (size_t)(m0 + row) * lda + k0 + lcol, va);
            bool vb = (n0 + row < N);
            cp_async16(sB + stage * stageBytes + (row * AST + lcol) * 4,
                       W + (size_t)(n0 + row) * ldb + k0 + lcol, vb);
        }
    };

    wmma::fragment<wmma::accumulator, 16, 16, 8, float> accf[2][4];
#pragma unroll
    for (int i = 0; i < 2; i++)
#pragma unroll
        for (int j = 0; j < 4; j++)
            wmma::fill_fragment(accf[i][j], 0.0f);

    const int ntiles = K / BK;
    issue(0, 0);
    cp_commit();

    for (int kt = 0; kt < ntiles; kt++) {
        int cur = kt & 1, nxt = cur ^ 1;
        if (kt + 1 < ntiles) issue(nxt, (kt + 1) * BK);
        cp_commit();
        cp_wait1();               // stage 'cur' is resident
        __syncthreads();

#pragma unroll
        for (int kk = 0; kk < BK; kk += 8) {
            wmma::fragment<wmma::matrix_a, 16, 16, 8, wmma::precision::tf32,
                           wmma::row_major> af[2];
            wmma::fragment<wmma::matrix_b, 16, 16, 8, wmma::precision::tf32,
                           wmma::col_major> bf[4];
#pragma unroll
            for (int i = 0; i < 2; i++)
                wmma::load_matrix_sync(af[i], &As[cur][wm * 32 + i * 16][kk], AST);
#pragma unroll
            for (int j = 0; j < 4; j++)
                wmma::load_matrix_sync(bf[j], &Bs[cur][wn * 64 + j * 16][kk], AST);
#pragma unroll
            for (int i = 0; i < 2; i++)
#pragma unroll
                for (int j = 0; j < 4; j++)
                    wmma::mma_sync(accf[i][j], af[i], bf[j], accf[i][j]);
        }
        __syncthreads();          // done reading 'cur' before it is refilled
    }

    // epilogue: stage fragments through (reused) smem, add bias (+ReLU)
    __syncthreads();
    float* sb = &As[0][0][0] + warp * 256;
#pragma unroll
    for (int i = 0; i < 2; i++) {
#pragma unroll
        for (int j = 0; j < 4; j++) {
            wmma::store_matrix_sync(sb, accf[i][j], 16, wmma::mem_row_major);
            __syncwarp();
            int r0 = m0 + wm * 32 + i * 16;
            int c0 = n0 + wn * 64 + j * 16;
#pragma unroll
            for (int q = 0; q < 8; q++) {
                int idx = lane + q * 32;
                int r = idx >> 4, c = idx & 15;
                if (r0 + r < Mb && c0 + c < N) {
                    float v = sb[idx] + bias[c0 + c];
                    if (RELU) v = fmaxf(v, 0.f);
                    C[(size_t)(r0 + r) * ldc + c0 + c] = v;
                }
            }
            __syncwarp();
        }
    }
}

// ---------------------------------------------------------------------------
// Flash attention (fp32): one CTA = one (b,h) head and a 64-query tile.
// ---------------------------------------------------------------------------
__global__ void __launch_bounds__(256)
attn_flash(const float* __restrict__ qkv, float* __restrict__ out)
{
    const int s0 = blockIdx.x * 64;
    const int bh = blockIdx.y;
    const int b  = bh / H_;
    const int h  = bh % H_;

    __shared__ float Qs[64 * 64];
    __shared__ float KPs[64 * 33];
    __shared__ float Vs[32 * 64];

    const int tid = threadIdx.x;
    const int tx = tid & 15, ty = tid >> 4;

    for (int idx = tid; idx < 64 * 64; idx += 256) {
        int m = idx >> 6, d = idx & 63;
        Qs[m * 64 + d] =
            qkv[((size_t)(s0 + m) * B_ + b) * D3_ + h * HD_ + d] * 0.125f;
    }

    float mrun[4], lrun[4], oacc[4][4];
#pragma unroll
    for (int i = 0; i < 4; i++) {
        mrun[i] = -1e30f;
        lrun[i] = 0.f;
#pragma unroll
        for (int j = 0; j < 4; j++) oacc[i][j] = 0.f;
    }
    __syncthreads();

    for (int t0 = 0; t0 < S_; t0 += 32) {
        for (int idx = tid; idx < 32 * 64; idx += 256) {
            int n = idx >> 6, d = idx & 63;
            size_t base = ((size_t)(t0 + n) * B_ + b) * D3_ + h * HD_ + d;
            KPs[d * 33 + n] = qkv[base + D_];
            Vs[n * 64 + d]  = qkv[base + 2 * D_];
        }
        __syncthreads();

        float sc[4][2];
#pragma unroll
        for (int i = 0; i < 4; i++) { sc[i][0] = 0.f; sc[i][1] = 0.f; }
        for (int d = 0; d < 64; d++) {
            float a[4], bb0, bb1;
#pragma unroll
            for (int i = 0; i < 4; i++) a[i] = Qs[(ty + i * 16) * 64 + d];
            bb0 = KPs[d * 33 + tx];
            bb1 = KPs[d * 33 + tx + 16];
#pragma unroll
            for (int i = 0; i < 4; i++) {
                sc[i][0] += a[i] * bb0;
                sc[i][1] += a[i] * bb1;
            }
        }
        __syncthreads();

#pragma unroll
        for (int i = 0; i < 4; i++) {
            float rmax = fmaxf(sc[i][0], sc[i][1]);
#pragma unroll
            for (int o = 8; o > 0; o >>= 1)
                rmax = fmaxf(rmax, __shfl_xor_sync(0xffffffffu, rmax, o));
            float mn   = fmaxf(mrun[i], rmax);
            float corr = __expf(mrun[i] - mn);
            mrun[i] = mn;
            float p0 = __expf(sc[i][0] - mn);
            float p1 = __expf(sc[i][1] - mn);
            float rsum = p0 + p1;
#pragma unroll
            for (int o = 8; o > 0; o >>= 1)
                rsum += __shfl_xor_sync(0xffffffffu, rsum, o);
            lrun[i] = lrun[i] * corr + rsum;
#pragma unroll
            for (int j = 0; j < 4; j++) oacc[i][j] *= corr;
            KPs[(ty + i * 16) * 33 + tx]      = p0;
            KPs[(ty + i * 16) * 33 + tx + 16] = p1;
        }
        __syncthreads();

        for (int t = 0; t < 32; t++) {
            float a[4], bb[4];
#pragma unroll
            for (int i = 0; i < 4; i++) a[i] = KPs[(ty + i * 16) * 33 + t];
#pragma unroll
            for (int j = 0; j < 4; j++) bb[j] = Vs[t * 64 + tx + j * 16];
#pragma unroll
            for (int i = 0; i < 4; i++)
#pragma unroll
                for (int j = 0; j < 4; j++) oacc[i][j] += a[i] * bb[j];
        }
        __syncthreads();
    }

#pragma unroll
    for (int i = 0; i < 4; i++) {
        int r = s0 + ty + i * 16;
        float inv = 1.f / lrun[i];
#pragma unroll
        for (int j = 0; j < 4; j++) {
            int c = tx + j * 16;
            out[((size_t)r * B_ + b) * D_ + h * HD_ + c] = oacc[i][j] * inv;
        }
    }
}

// ---------------------------------------------------------------------------
// out = LayerNorm(a + r) * gamma + beta
// ---------------------------------------------------------------------------
__global__ void __launch_bounds__(256)
add_ln_kernel(const float* __restrict__ a, const float* __restrict__ r,
              const float* __restrict__ gamma, const float* __restrict__ beta,
              float* __restrict__ out)
{
    const int row = blockIdx.x;
    __shared__ float buf[D_];
    __shared__ float ws[8], wq[8];
    __shared__ float red[2];
    const int tid = threadIdx.x;
    const size_t base = (size_t)row * D_;

    float s = 0.f, sq = 0.f;
    for (int i = tid; i < D_; i += 256) {
        float v = a[base + i] + r[base + i];
        buf[i] = v;
        s += v;
        sq += v * v;
    }
#pragma unroll
    for (int o = 16; o > 0; o >>= 1) {
        s  += __shfl_xor_sync(0xffffffffu, s, o);
        sq += __shfl_xor_sync(0xffffffffu, sq, o);
    }
    int lane = tid & 31, wid = tid >> 5;
    if (lane == 0) { ws[wid] = s; wq[wid] = sq; }
    __syncthreads();
    if (tid == 0) {
        float Ssum = 0.f, Q = 0.f;
#pragma unroll
        for (int w = 0; w < 8; w++) { Ssum += ws[w]; Q += wq[w]; }
        float mu  = Ssum * (1.0f / D_);
        float var = Q * (1.0f / D_) - mu * mu;
        red[0] = mu;
        red[1] = rsqrtf(var + 1e-5f);
    }
    __syncthreads();
    float mu = red[0], rstd = red[1];
    for (int i = tid; i < D_; i += 256)
        out[base + i] = (buf[i] - mu) * rstd * gamma[i] + beta[i];
}

// ---------------------------------------------------------------------------
extern "C" void kernel_launch(void* const* d_in, const int* in_sizes, int n_in,
                              void* d_out, int out_size)
{
    (void)in_sizes; (void)n_in; (void)out_size;
    const float* src  = (const float*)d_in[0];
    const float* inw  = (const float*)d_in[1];
    const float* inb  = (const float*)d_in[2];
    const float* outw = (const float*)d_in[3];
    const float* outb = (const float*)d_in[4];
    const float* g1   = (const float*)d_in[5];
    const float* be1  = (const float*)d_in[6];
    const float* g2   = (const float*)d_in[7];
    const float* be2  = (const float*)d_in[8];
    const float* w1   = (const float*)d_in[9];
    const float* b1   = (const float*)d_in[10];
    const float* w2   = (const float*)d_in[11];
    const float* b2   = (const float*)d_in[12];
    float* out = (float*)d_out;

    float *qkv, *attn, *proj, *x1, *hbuf, *moe;
    cudaGetSymbolAddress((void**)&qkv,  g_qkv);
    cudaGetSymbolAddress((void**)&attn, g_attn);
    cudaGetSymbolAddress((void**)&proj, g_proj);
    cudaGetSymbolAddress((void**)&x1,   g_x1);
    cudaGetSymbolAddress((void**)&hbuf, g_h);
    cudaGetSymbolAddress((void**)&moe,  g_moe);

    dim3 blk(256);

    // 1) qkv = src @ in_proj_w^T + b   [8192 x 3072]
    gemm_tf32<false, false><<<dim3(D3_ / 128, NTOK / 128), blk>>>(
        src, D_, inw, D_, inb, qkv, D3_, NTOK, D3_, D_, 0, 0);

    // 2) attention -> attn [8192 x 1024]
    attn_flash<<<dim3(S_ / 64, B_ * H_), blk>>>(qkv, attn);

    // 3) proj = attn @ out_proj_w^T + b [8192 x 1024]
    gemm_tf32<false, false><<<dim3(D_ / 128, NTOK / 128), blk>>>(
        attn, D_, outw, D_, outb, proj, D_, NTOK, D_, D_, 0, 0);

    // 4) x1 = LN(src + proj)
    add_ln_kernel<<<NTOK, blk>>>(src, proj, g1, be1, x1);

    // 5) MoE: ALL experts in two batched launches (68 M-tiles total)
    gemm_tf32<true, true><<<dim3(F_ / 128, 68), blk>>>(
        x1, D_, w1, D_, b1, hbuf, F_, NTOK, F_, D_,
        (size_t)F_ * D_, F_);
    gemm_tf32<false, true><<<dim3(D_ / 128, 68), blk>>>(
        hbuf, F_, w2, F_, b2, moe, D_, NTOK, D_, F_,
        (size_t)D_ * F_, D_);

    // 6) out = LN(x1 + moe)
    add_ln_kernel<<<NTOK, blk>>>(x1, moe, g2, be2, out);
}

// round 5
// speedup vs baseline: 2.8897x; 1.1076x over previous
#include <cuda_runtime.h>
#include <mma.h>
#include <math.h>
#include <cstdint>

using namespace nvcuda;

#define S_  1024
#define B_  8
#define D_  1024
#define H_  16
#define HD_ 64
#define F_  4096
#define E_  8
#define NTOK (S_ * B_)      // 8192 tokens
#define D3_ (3 * D_)        // 3072

// ---------------- scratch (device globals: no allocs allowed) ----------------
__device__ float g_qkv [(size_t)NTOK * D3_];   // 96 MB
__device__ float g_attn[(size_t)NTOK * D_];    // 32 MB
__device__ float g_proj[(size_t)NTOK * D_];    // 32 MB
__device__ float g_x1  [(size_t)NTOK * D_];    // 32 MB
__device__ float g_h   [(size_t)NTOK * F_];    // 128 MB
__device__ float g_moe [(size_t)NTOK * D_];    // 32 MB

// ---------------------------------------------------------------------------
// cp.async helpers
// ---------------------------------------------------------------------------
__device__ __forceinline__ void cp_async16(unsigned int smem_addr,
                                           const void* gptr, bool valid)
{
    int sz = valid ? 16 : 0;
    asm volatile("cp.async.cg.shared.global [%0], [%1], 16, %2;\n"
                 :: "r"(smem_addr), "l"(gptr), "r"(sz));
}
__device__ __forceinline__ void cp_commit() {
    asm volatile("cp.async.commit_group;\n");
}
__device__ __forceinline__ void cp_wait1() {
    asm volatile("cp.async.wait_group 1;\n");
}

// ---------------------------------------------------------------------------
// tf32 WMMA GEMM with 2-stage cp.async pipeline.  (unchanged from R4)
//   C[M,N] = A[M,K] @ W[N,K]^T + bias[N]   (optional ReLU)
// ---------------------------------------------------------------------------
#define BK  16
#define AST 20   // smem row stride (16 + 4 pad)

template<bool RELU, bool MOE>
__global__ void __launch_bounds__(256, 2)
gemm_tf32(const float* __restrict__ Abase, int lda,
          const float* __restrict__ Wbase, int ldb,
          const float* __restrict__ biasbase,
          float* __restrict__ C, int ldc,
          int M, int N, int K,
          size_t wstride, int bstride)
{
    __shared__ float As[2][128][AST];
    __shared__ float Bs[2][128][AST];

    const int tid  = threadIdx.x;
    const int warp = tid >> 5;
    const int lane = tid & 31;
    const int wm   = warp & 3;
    const int wn   = warp >> 2;
    const int n0   = blockIdx.x * 128;

    int m0, Mb;
    const float* A = Abase;
    const float* W = Wbase;
    const float* bias = biasbase;
    if (MOE) {
        const int tcnt[8] = {54, 7, 2, 1, 1, 1, 1, 1};
        const int toff[8] = {0, 6852, 7709, 7963, 8070, 8125, 8157, 8177};
        const int tn[8]   = {6852, 857, 254, 107, 55, 32, 20, 15};
        int y = blockIdx.y, e = 0, acc = 0;
        while (y >= acc + tcnt[e]) { acc += tcnt[e]; e++; }
        m0 = toff[e] + (y - acc) * 128;
        Mb = toff[e] + tn[e];
        W    = Wbase + (size_t)e * wstride;
        bias = biasbase + (size_t)e * bstride;
    } else {
        m0 = blockIdx.y * 128;
        Mb = M;
    }

    const int lrow = tid >> 2;           // 0..63
    const int lcol = (tid & 3) << 2;     // 0,4,8,12

    unsigned int sA = (unsigned int)__cvta_generic_to_shared(&As[0][0][0]);
    unsigned int sB = (unsigned int)__cvta_generic_to_shared(&Bs[0][0][0]);
    const unsigned int stageBytes = 128 * AST * 4;

    auto issue = [&](int stage, int k0) {
#pragma unroll
        for (int t = 0; t < 2; t++) {
            int row = lrow + t * 64;
            bool va = (m0 + row < Mb);
            cp_async16(sA + stage * stageBytes + (row * AST + lcol) * 4,
                       A + (size_t)(m0 + row) * lda + k0 + lcol, va);
            bool vb = (n0 + row < N);
            cp_async16(sB + stage * stageBytes + (row * AST + lcol) * 4,
                       W + (size_t)(n0 + row) * ldb + k0 + lcol, vb);
        }
    };

    wmma::fragment<wmma::accumulator, 16, 16, 8, float> accf[2][4];
#pragma unroll
    for (int i = 0; i < 2; i++)
#pragma unroll
        for (int j = 0; j < 4; j++)
            wmma::fill_fragment(accf[i][j], 0.0f);

    const int ntiles = K / BK;
    issue(0, 0);
    cp_commit();

    for (int kt = 0; kt < ntiles; kt++) {
        int cur = kt & 1, nxt = cur ^ 1;
        if (kt + 1 < ntiles) issue(nxt, (kt + 1) * BK);
        cp_commit();
        cp_wait1();
        __syncthreads();

#pragma unroll
        for (int kk = 0; kk < BK; kk += 8) {
            wmma::fragment<wmma::matrix_a, 16, 16, 8, wmma::precision::tf32,
                           wmma::row_major> af[2];
            wmma::fragment<wmma::matrix_b, 16, 16, 8, wmma::precision::tf32,
                           wmma::col_major> bf[4];
#pragma unroll
            for (int i = 0; i < 2; i++)
                wmma::load_matrix_sync(af[i], &As[cur][wm * 32 + i * 16][kk], AST);
#pragma unroll
            for (int j = 0; j < 4; j++)
                wmma::load_matrix_sync(bf[j], &Bs[cur][wn * 64 + j * 16][kk], AST);
#pragma unroll
            for (int i = 0; i < 2; i++)
#pragma unroll
                for (int j = 0; j < 4; j++)
                    wmma::mma_sync(accf[i][j], af[i], bf[j], accf[i][j]);
        }
        __syncthreads();
    }

    __syncthreads();
    float* sb = &As[0][0][0] + warp * 256;
#pragma unroll
    for (int i = 0; i < 2; i++) {
#pragma unroll
        for (int j = 0; j < 4; j++) {
            wmma::store_matrix_sync(sb, accf[i][j], 16, wmma::mem_row_major);
            __syncwarp();
            int r0 = m0 + wm * 32 + i * 16;
            int c0 = n0 + wn * 64 + j * 16;
#pragma unroll
            for (int q = 0; q < 8; q++) {
                int idx = lane + q * 32;
                int r = idx >> 4, c = idx & 15;
                if (r0 + r < Mb && c0 + c < N) {
                    float v = sb[idx] + bias[c0 + c];
                    if (RELU) v = fmaxf(v, 0.f);
                    C[(size_t)(r0 + r) * ldc + c0 + c] = v;
                }
            }
            __syncwarp();
        }
    }
}

// ---------------------------------------------------------------------------
// Flash attention, tf32 WMMA. One CTA = (b,h) head + 64-query tile.
// 64-key tiles; S and PV on tensor cores; softmax + O rescale scalar in smem.
// K stored [key][d] -> matrix_b col_major; V stored [key][d] -> matrix_b
// row_major. All tensor inputs RN-rounded to tf32 once at smem-fill time.
// ---------------------------------------------------------------------------
#define AS 68                                   // smem row stride (64 + 4)
#define ATT_SMEM ((5 * 64 * AS + 192) * 4)      // 87808 bytes

__global__ void __launch_bounds__(256)
attn_wmma(const float* __restrict__ qkv, float* __restrict__ out)
{
    extern __shared__ float dsm[];
    float* Qs = dsm;
    float* Ks = Qs + 64 * AS;
    float* Vs = Ks + 64 * AS;
    float* SP = Vs + 64 * AS;
    float* Os = SP + 64 * AS;
    float* mrow = Os + 64 * AS;
    float* lrow = mrow + 64;
    float* crow = mrow + 128;

    const int s0 = blockIdx.x * 64;
    const int bh = blockIdx.y;
    const int b = bh >> 4, h = bh & 15;          // H_ = 16
    const int tid  = threadIdx.x;
    const int warp = tid >> 5;
    const int wm = warp & 3, wn = warp >> 2;     // 4 x 2 warp grid

    // ---- load Q (scale by 1/8, RN round to tf32) ----
#pragma unroll
    for (int it = 0; it < 4; it++) {
        int i  = tid + it * 256;
        int r  = i >> 4;
        int c4 = (i & 15) << 2;
        float4 v = *(const float4*)(qkv + ((size_t)(s0 + r) * B_ + b) * D3_
                                    + h * HD_ + c4);
        float4 w;
        w.x = wmma::__float_to_tf32(v.x * 0.125f);
        w.y = wmma::__float_to_tf32(v.y * 0.125f);
        w.z = wmma::__float_to_tf32(v.z * 0.125f);
        w.w = wmma::__float_to_tf32(v.w * 0.125f);
        *(float4*)(Qs + r * AS + c4) = w;
    }
    for (int i = tid; i < 64 * AS; i += 256) Os[i] = 0.f;
    if (tid < 64) { mrow[tid] = -1e30f; lrow[tid] = 0.f; }
    __syncthreads();

    const int r = tid >> 2;       // softmax row (0..63)
    const int q = tid & 3;        // quad lane (16 cols each)

    for (int t0 = 0; t0 < S_; t0 += 64) {
        // ---- load K/V tile (RN round to tf32) ----
#pragma unroll
        for (int it = 0; it < 4; it++) {
            int i  = tid + it * 256;
            int rr = i >> 4;
            int c4 = (i & 15) << 2;
            size_t base = ((size_t)(t0 + rr) * B_ + b) * D3_ + h * HD_ + c4;
            float4 kv = *(const float4*)(qkv + base + D_);
            float4 vv = *(const float4*)(qkv + base + 2 * D_);
            float4 ko, vo;
            ko.x = wmma::__float_to_tf32(kv.x);
            ko.y = wmma::__float_to_tf32(kv.y);
            ko.z = wmma::__float_to_tf32(kv.z);
            ko.w = wmma::__float_to_tf32(kv.w);
            vo.x = wmma::__float_to_tf32(vv.x);
            vo.y = wmma::__float_to_tf32(vv.y);
            vo.z = wmma::__float_to_tf32(vv.z);
            vo.w = wmma::__float_to_tf32(vv.w);
            *(float4*)(Ks + rr * AS + c4) = ko;
            *(float4*)(Vs + rr * AS + c4) = vo;
        }
        __syncthreads();

        // ---- S = Q @ K^T  (warp tile 16x32) ----
        {
            wmma::fragment<wmma::accumulator, 16, 16, 8, float> sf[2];
            wmma::fill_fragment(sf[0], 0.f);
            wmma::fill_fragment(sf[1], 0.f);
#pragma unroll
            for (int kk = 0; kk < 64; kk += 8) {
                wmma::fragment<wmma::matrix_a, 16, 16, 8,
                               wmma::precision::tf32, wmma::row_major> af;
                wmma::load_matrix_sync(af, Qs + wm * 16 * AS + kk, AS);
#pragma unroll
                for (int j = 0; j < 2; j++) {
                    wmma::fragment<wmma::matrix_b, 16, 16, 8,
                                   wmma::precision::tf32, wmma::col_major> bf;
                    wmma::load_matrix_sync(bf, Ks + (wn * 32 + j * 16) * AS + kk,
                                           AS);
                    wmma::mma_sync(sf[j], af, bf, sf[j]);
                }
            }
#pragma unroll
            for (int j = 0; j < 2; j++)
                wmma::store_matrix_sync(SP + wm * 16 * AS + wn * 32 + j * 16,
                                        sf[j], AS, wmma::mem_row_major);
        }
        __syncthreads();

        // ---- online softmax (scalar, 4 threads per row) ----
        {
            float* sp = SP + r * AS + q * 16;
            float mx = sp[0];
#pragma unroll
            for (int c = 1; c < 16; c++) mx = fmaxf(mx, sp[c]);
            mx = fmaxf(mx, __shfl_xor_sync(0xffffffffu, mx, 1));
            mx = fmaxf(mx, __shfl_xor_sync(0xffffffffu, mx, 2));
            float mold = mrow[r];
            float mnew = fmaxf(mold, mx);
            float sum = 0.f;
#pragma unroll
            for (int c = 0; c < 16; c++) {
                float p = __expf(sp[c] - mnew);
                sum += p;
                sp[c] = wmma::__float_to_tf32(p);
            }
            sum += __shfl_xor_sync(0xffffffffu, sum, 1);
            sum += __shfl_xor_sync(0xffffffffu, sum, 2);
            if (q == 0) {
                float corr = __expf(mold - mnew);
                mrow[r] = mnew;
                lrow[r] = lrow[r] * corr + sum;
                crow[r] = corr;
            }
        }
        __syncthreads();

        // ---- PV = P @ V  (fresh accumulators) ----
        {
            wmma::fragment<wmma::accumulator, 16, 16, 8, float> pf[2];
            wmma::fill_fragment(pf[0], 0.f);
            wmma::fill_fragment(pf[1], 0.f);
#pragma unroll
            for (int kk = 0; kk < 64; kk += 8) {
                wmma::fragment<wmma::matrix_a, 16, 16, 8,
                               wmma::precision::tf32, wmma::row_major> af;
                wmma::load_matrix_sync(af, SP + wm * 16 * AS + kk, AS);
#pragma unroll
                for (int j = 0; j < 2; j++) {
                    wmma::fragment<wmma::matrix_b, 16, 16, 8,
                                   wmma::precision::tf32, wmma::row_major> bf;
                    wmma::load_matrix_sync(bf, Vs + kk * AS + wn * 32 + j * 16,
                                           AS);
                    wmma::mma_sync(pf[j], af, bf, pf[j]);
                }
            }
            __syncthreads();   // all P reads complete before overwrite
#pragma unroll
            for (int j = 0; j < 2; j++)
                wmma::store_matrix_sync(SP + wm * 16 * AS + wn * 32 + j * 16,
                                        pf[j], AS, wmma::mem_row_major);
        }
        __syncthreads();

        // ---- O = O*corr + PV ----
        {
            float corr = crow[r];
            float* os = Os + r * AS + q * 16;
            float* pv = SP + r * AS + q * 16;
#pragma unroll
            for (int c = 0; c < 16; c++)
                os[c] = os[c] * corr + pv[c];
        }
        __syncthreads();
    }

    // ---- writeout ----
    {
        float inv = 1.f / lrow[r];
        float* os = Os + r * AS + q * 16;
        float* dst = out + ((size_t)(s0 + r) * B_ + b) * D_ + h * HD_ + q * 16;
#pragma unroll
        for (int c = 0; c < 16; c++)
            dst[c] = os[c] * inv;
    }
}

// ---------------------------------------------------------------------------
// out = LayerNorm(a + r) * gamma + beta
// ---------------------------------------------------------------------------
__global__ void __launch_bounds__(256)
add_ln_kernel(const float* __restrict__ a, const float* __restrict__ r,
              const float* __restrict__ gamma, const float* __restrict__ beta,
              float* __restrict__ out)
{
    const int row = blockIdx.x;
    __shared__ float buf[D_];
    __shared__ float ws[8], wq[8];
    __shared__ float red[2];
    const int tid = threadIdx.x;
    const size_t base = (size_t)row * D_;

    float s = 0.f, sq = 0.f;
    for (int i = tid; i < D_; i += 256) {
        float v = a[base + i] + r[base + i];
        buf[i] = v;
        s += v;
        sq += v * v;
    }
#pragma unroll
    for (int o = 16; o > 0; o >>= 1) {
        s  += __shfl_xor_sync(0xffffffffu, s, o);
        sq += __shfl_xor_sync(0xffffffffu, sq, o);
    }
    int lane = tid & 31, wid = tid >> 5;
    if (lane == 0) { ws[wid] = s; wq[wid] = sq; }
    __syncthreads();
    if (tid == 0) {
        float Ssum = 0.f, Q = 0.f;
#pragma unroll
        for (int w = 0; w < 8; w++) { Ssum += ws[w]; Q += wq[w]; }
        float mu  = Ssum * (1.0f / D_);
        float var = Q * (1.0f / D_) - mu * mu;
        red[0] = mu;
        red[1] = rsqrtf(var + 1e-5f);
    }
    __syncthreads();
    float mu = red[0], rstd = red[1];
    for (int i = tid; i < D_; i += 256)
        out[base + i] = (buf[i] - mu) * rstd * gamma[i] + beta[i];
}

// ---------------------------------------------------------------------------
extern "C" void kernel_launch(void* const* d_in, const int* in_sizes, int n_in,
                              void* d_out, int out_size)
{
    (void)in_sizes; (void)n_in; (void)out_size;
    const float* src  = (const float*)d_in[0];
    const float* inw  = (const float*)d_in[1];
    const float* inb  = (const float*)d_in[2];
    const float* outw = (const float*)d_in[3];
    const float* outb = (const float*)d_in[4];
    const float* g1   = (const float*)d_in[5];
    const float* be1  = (const float*)d_in[6];
    const float* g2   = (const float*)d_in[7];
    const float* be2  = (const float*)d_in[8];
    const float* w1   = (const float*)d_in[9];
    const float* b1   = (const float*)d_in[10];
    const float* w2   = (const float*)d_in[11];
    const float* b2   = (const float*)d_in[12];
    float* out = (float*)d_out;

    float *qkv, *attn, *proj, *x1, *hbuf, *moe;
    cudaGetSymbolAddress((void**)&qkv,  g_qkv);
    cudaGetSymbolAddress((void**)&attn, g_attn);
    cudaGetSymbolAddress((void**)&proj, g_proj);
    cudaGetSymbolAddress((void**)&x1,   g_x1);
    cudaGetSymbolAddress((void**)&hbuf, g_h);
    cudaGetSymbolAddress((void**)&moe,  g_moe);

    dim3 blk(256);

    // 1) qkv = src @ in_proj_w^T + b   [8192 x 3072]
    gemm_tf32<false, false><<<dim3(D3_ / 128, NTOK / 128), blk>>>(
        src, D_, inw, D_, inb, qkv, D3_, NTOK, D3_, D_, 0, 0);

    // 2) attention -> attn [8192 x 1024]  (tf32 wmma flash)
    cudaFuncSetAttribute(attn_wmma,
                         cudaFuncAttributeMaxDynamicSharedMemorySize, ATT_SMEM);
    attn_wmma<<<dim3(S_ / 64, B_ * H_), blk, ATT_SMEM>>>(qkv, attn);

    // 3) proj = attn @ out_proj_w^T + b [8192 x 1024]
    gemm_tf32<false, false><<<dim3(D_ / 128, NTOK / 128), blk>>>(
        attn, D_, outw, D_, outb, proj, D_, NTOK, D_, D_, 0, 0);

    // 4) x1 = LN(src + proj)
    add_ln_kernel<<<NTOK, blk>>>(src, proj, g1, be1, x1);

    // 5) MoE: ALL experts in two batched launches (68 M-tiles total)
    gemm_tf32<true, true><<<dim3(F_ / 128, 68), blk>>>(
        x1, D_, w1, D_, b1, hbuf, F_, NTOK, F_, D_,
        (size_t)F_ * D_, F_);
    gemm_tf32<false, true><<<dim3(D_ / 128, 68), blk>>>(
        hbuf, F_, w2, F_, b2, moe, D_, NTOK, D_, F_,
        (size_t)D_ * F_, D_);

    // 6) out = LN(x1 + moe)
    add_ln_kernel<<<NTOK, blk>>>(x1, moe, g2, be2, out);
}

// round 6
// speedup vs baseline: 3.3600x; 1.1628x over previous
#include <cuda_runtime.h>
#include <mma.h>
#include <math.h>
#include <cstdint>

using namespace nvcuda;

#define S_  1024
#define B_  8
#define D_  1024
#define H_  16
#define HD_ 64
#define F_  4096
#define E_  8
#define NTOK (S_ * B_)      // 8192 tokens
#define D3_ (3 * D_)        // 3072

// ---------------- scratch (device globals: no allocs allowed) ----------------
__device__ float g_qkv [(size_t)NTOK * D3_];   // 96 MB
__device__ float g_attn[(size_t)NTOK * D_];    // 32 MB
__device__ float g_proj[(size_t)NTOK * D_];    // 32 MB
__device__ float g_x1  [(size_t)NTOK * D_];    // 32 MB
__device__ float g_h   [(size_t)NTOK * F_];    // 128 MB
__device__ float g_moe [(size_t)NTOK * D_];    // 32 MB

// ---------------------------------------------------------------------------
// cp.async helpers
// ---------------------------------------------------------------------------
__device__ __forceinline__ void cp_async16(unsigned int smem_addr,
                                           const void* gptr, bool valid)
{
    int sz = valid ? 16 : 0;
    asm volatile("cp.async.cg.shared.global [%0], [%1], 16, %2;\n"
                 :: "r"(smem_addr), "l"(gptr), "r"(sz));
}
__device__ __forceinline__ void cp_commit() {
    asm volatile("cp.async.commit_group;\n");
}
__device__ __forceinline__ void cp_wait1() {
    asm volatile("cp.async.wait_group 1;\n");
}

// raw tf32 mma, accumulate in place
__device__ __forceinline__ void mma_tf32(float d[4], const unsigned a[4],
                                         const unsigned b[2])
{
    asm volatile(
        "mma.sync.aligned.m16n8k8.row.col.f32.tf32.tf32.f32 "
        "{%0,%1,%2,%3}, {%4,%5,%6,%7}, {%8,%9}, {%0,%1,%2,%3};"
        : "+f"(d[0]), "+f"(d[1]), "+f"(d[2]), "+f"(d[3])
        : "r"(a[0]), "r"(a[1]), "r"(a[2]), "r"(a[3]), "r"(b[0]), "r"(b[1]));
}
__device__ __forceinline__ float tf32_rna(float x) {
    unsigned u;
    asm("cvt.rna.tf32.f32 %0, %1;" : "=r"(u) : "f"(x));
    return __uint_as_float(u);
}

// ---------------------------------------------------------------------------
// tf32 WMMA GEMM with 2-stage cp.async pipeline.  (unchanged from R4/R5)
// ---------------------------------------------------------------------------
#define BK  16
#define AST 20

template<bool RELU, bool MOE>
__global__ void __launch_bounds__(256, 2)
gemm_tf32(const float* __restrict__ Abase, int lda,
          const float* __restrict__ Wbase, int ldb,
          const float* __restrict__ biasbase,
          float* __restrict__ C, int ldc,
          int M, int N, int K,
          size_t wstride, int bstride)
{
    __shared__ float As[2][128][AST];
    __shared__ float Bs[2][128][AST];

    const int tid  = threadIdx.x;
    const int warp = tid >> 5;
    const int lane = tid & 31;
    const int wm   = warp & 3;
    const int wn   = warp >> 2;
    const int n0   = blockIdx.x * 128;

    int m0, Mb;
    const float* A = Abase;
    const float* W = Wbase;
    const float* bias = biasbase;
    if (MOE) {
        const int tcnt[8] = {54, 7, 2, 1, 1, 1, 1, 1};
        const int toff[8] = {0, 6852, 7709, 7963, 8070, 8125, 8157, 8177};
        const int tn[8]   = {6852, 857, 254, 107, 55, 32, 20, 15};
        int y = blockIdx.y, e = 0, acc = 0;
        while (y >= acc + tcnt[e]) { acc += tcnt[e]; e++; }
        m0 = toff[e] + (y - acc) * 128;
        Mb = toff[e] + tn[e];
        W    = Wbase + (size_t)e * wstride;
        bias = biasbase + (size_t)e * bstride;
    } else {
        m0 = blockIdx.y * 128;
        Mb = M;
    }

    const int lrow = tid >> 2;
    const int lcol = (tid & 3) << 2;

    unsigned int sA = (unsigned int)__cvta_generic_to_shared(&As[0][0][0]);
    unsigned int sB = (unsigned int)__cvta_generic_to_shared(&Bs[0][0][0]);
    const unsigned int stageBytes = 128 * AST * 4;

    auto issue = [&](int stage, int k0) {
#pragma unroll
        for (int t = 0; t < 2; t++) {
            int row = lrow + t * 64;
            bool va = (m0 + row < Mb);
            cp_async16(sA + stage * stageBytes + (row * AST + lcol) * 4,
                       A + (size_t)(m0 + row) * lda + k0 + lcol, va);
            bool vb = (n0 + row < N);
            cp_async16(sB + stage * stageBytes + (row * AST + lcol) * 4,
                       W + (size_t)(n0 + row) * ldb + k0 + lcol, vb);
        }
    };

    wmma::fragment<wmma::accumulator, 16, 16, 8, float> accf[2][4];
#pragma unroll
    for (int i = 0; i < 2; i++)
#pragma unroll
        for (int j = 0; j < 4; j++)
            wmma::fill_fragment(accf[i][j], 0.0f);

    const int ntiles = K / BK;
    issue(0, 0);
    cp_commit();

    for (int kt = 0; kt < ntiles; kt++) {
        int cur = kt & 1, nxt = cur ^ 1;
        if (kt + 1 < ntiles) issue(nxt, (kt + 1) * BK);
        cp_commit();
        cp_wait1();
        __syncthreads();

#pragma unroll
        for (int kk = 0; kk < BK; kk += 8) {
            wmma::fragment<wmma::matrix_a, 16, 16, 8, wmma::precision::tf32,
                           wmma::row_major> af[2];
            wmma::fragment<wmma::matrix_b, 16, 16, 8, wmma::precision::tf32,
                           wmma::col_major> bf[4];
#pragma unroll
            for (int i = 0; i < 2; i++)
                wmma::load_matrix_sync(af[i], &As[cur][wm * 32 + i * 16][kk], AST);
#pragma unroll
            for (int j = 0; j < 4; j++)
                wmma::load_matrix_sync(bf[j], &Bs[cur][wn * 64 + j * 16][kk], AST);
#pragma unroll
            for (int i = 0; i < 2; i++)
#pragma unroll
                for (int j = 0; j < 4; j++)
                    wmma::mma_sync(accf[i][j], af[i], bf[j], accf[i][j]);
        }
        __syncthreads();
    }

    __syncthreads();
    float* sb = &As[0][0][0] + warp * 256;
#pragma unroll
    for (int i = 0; i < 2; i++) {
#pragma unroll
        for (int j = 0; j < 4; j++) {
            wmma::store_matrix_sync(sb, accf[i][j], 16, wmma::mem_row_major);
            __syncwarp();
            int r0 = m0 + wm * 32 + i * 16;
            int c0 = n0 + wn * 64 + j * 16;
#pragma unroll
            for (int q = 0; q < 8; q++) {
                int idx = lane + q * 32;
                int r = idx >> 4, c = idx & 15;
                if (r0 + r < Mb && c0 + c < N) {
                    float v = sb[idx] + bias[c0 + c];
                    if (RELU) v = fmaxf(v, 0.f);
                    C[(size_t)(r0 + r) * ldc + c0 + c] = v;
                }
            }
            __syncwarp();
        }
    }
}

// ---------------------------------------------------------------------------
// Flash attention, register-resident FA2 with raw mma.m16n8k8 tf32.
// CTA = 128 queries x one (b,h) head; 8 warps x 16 query rows.
// Q in a-fragments (regs, loaded once). S in acc regs; softmax in regs
// (quad shfl reductions). O in acc regs across tiles (in-register rescale).
// Only P goes through (warp-private) smem. 2 CTA syncs per 64-key tile.
//
// mma.m16n8k8 layouts (lane = tid&31, ra = lane>>2, q4 = lane&3):
//   A: a0(r=ra,k=q4) a1(r=ra+8,k=q4) a2(r=ra,k=q4+4) a3(r=ra+8,k=q4+4)
//   B: b0(k=q4,n=ra) b1(k=q4+4,n=ra)
//   C: c0(r=ra,c=2q4) c1(c=2q4+1) c2(r=ra+8,c=2q4) c3(c=2q4+1)
// ---------------------------------------------------------------------------
#define PST 68
#define ATT_SMEM ((2 * 64 * PST + 8 * 16 * PST) * 4)   // 69632 bytes

__global__ void __launch_bounds__(256)
attn_mma(const float* __restrict__ qkv, float* __restrict__ out)
{
    extern __shared__ float sm[];
    float* Ks = sm;                  // 64 x PST
    float* Vs = Ks + 64 * PST;       // 64 x PST
    float* Ps = Vs + 64 * PST;       // 8 x 16 x PST (warp-private)

    const int tid  = threadIdx.x;
    const int warp = tid >> 5, lane = tid & 31;
    const int ra = lane >> 2, q4 = lane & 3;
    const int s0 = blockIdx.x * 128;
    const int b  = blockIdx.y >> 4, h = blockIdx.y & 15;
    float* Pw = Ps + warp * 16 * PST;

    // ---- Q a-fragments (scaled by 1/8), loaded once ----
    unsigned qa[8][4];
    {
        const int r0 = s0 + warp * 16;
        const float* rowA = qkv + ((size_t)(r0 + ra) * B_ + b) * D3_ + h * HD_;
        const float* rowB = qkv + ((size_t)(r0 + ra + 8) * B_ + b) * D3_ + h * HD_;
#pragma unroll
        for (int j = 0; j < 8; j++) {
            qa[j][0] = __float_as_uint(rowA[8 * j + q4] * 0.125f);
            qa[j][1] = __float_as_uint(rowB[8 * j + q4] * 0.125f);
            qa[j][2] = __float_as_uint(rowA[8 * j + q4 + 4] * 0.125f);
            qa[j][3] = __float_as_uint(rowB[8 * j + q4 + 4] * 0.125f);
        }
    }

    float oa[8][4];
#pragma unroll
    for (int j = 0; j < 8; j++)
#pragma unroll
        for (int e = 0; e < 4; e++) oa[j][e] = 0.f;
    float m_a = -1e30f, m_b = -1e30f, l_a = 0.f, l_b = 0.f;

    for (int t0 = 0; t0 < S_; t0 += 64) {
        // ---- cooperative K/V tile load (raw fp32; HMMA truncates) ----
#pragma unroll
        for (int it = 0; it < 4; it++) {
            int i  = tid + it * 256;          // 0..1023
            int rr = i >> 4;
            int c4 = (i & 15) << 2;
            size_t base = ((size_t)(t0 + rr) * B_ + b) * D3_ + h * HD_ + c4;
            *(float4*)(Ks + rr * PST + c4) = *(const float4*)(qkv + base + D_);
            *(float4*)(Vs + rr * PST + c4) = *(const float4*)(qkv + base + 2 * D_);
        }
        __syncthreads();

        // ---- S = Q @ K^T : 8 n8-tiles (64 keys), 8 k-steps ----
        float sacc[8][4];
#pragma unroll
        for (int j = 0; j < 8; j++)
#pragma unroll
            for (int e = 0; e < 4; e++) sacc[j][e] = 0.f;
#pragma unroll
        for (int kk = 0; kk < 8; kk++) {
#pragma unroll
            for (int j = 0; j < 8; j++) {
                unsigned bb[2];
                const float* kr = Ks + (8 * j + ra) * PST + 8 * kk + q4;
                bb[0] = __float_as_uint(kr[0]);
                bb[1] = __float_as_uint(kr[4]);
                mma_tf32(sacc[j], qa[kk], bb);
            }
        }

        // ---- online softmax in registers ----
        float mxa = sacc[0][0], mxb = sacc[0][2];
#pragma unroll
        for (int j = 0; j < 8; j++) {
            mxa = fmaxf(mxa, fmaxf(sacc[j][0], sacc[j][1]));
            mxb = fmaxf(mxb, fmaxf(sacc[j][2], sacc[j][3]));
        }
        mxa = fmaxf(mxa, __shfl_xor_sync(0xffffffffu, mxa, 1));
        mxa = fmaxf(mxa, __shfl_xor_sync(0xffffffffu, mxa, 2));
        mxb = fmaxf(mxb, __shfl_xor_sync(0xffffffffu, mxb, 1));
        mxb = fmaxf(mxb, __shfl_xor_sync(0xffffffffu, mxb, 2));

        float mna = fmaxf(m_a, mxa), mnb = fmaxf(m_b, mxb);
        float ca = __expf(m_a - mna), cb = __expf(m_b - mnb);
        m_a = mna; m_b = mnb;

        float sa = 0.f, sb2 = 0.f;
#pragma unroll
        for (int j = 0; j < 8; j++) {
            float p0 = tf32_rna(__expf(sacc[j][0] - mna));
            float p1 = tf32_rna(__expf(sacc[j][1] - mna));
            float p2 = tf32_rna(__expf(sacc[j][2] - mnb));
            float p3 = tf32_rna(__expf(sacc[j][3] - mnb));
            sa  += p0 + p1;
            sb2 += p2 + p3;
            *(float2*)(Pw + ra * PST + 8 * j + 2 * q4)       = make_float2(p0, p1);
            *(float2*)(Pw + (ra + 8) * PST + 8 * j + 2 * q4) = make_float2(p2, p3);
        }
        sa  += __shfl_xor_sync(0xffffffffu, sa, 1);
        sa  += __shfl_xor_sync(0xffffffffu, sa, 2);
        sb2 += __shfl_xor_sync(0xffffffffu, sb2, 1);
        sb2 += __shfl_xor_sync(0xffffffffu, sb2, 2);
        l_a = l_a * ca + sa;
        l_b = l_b * cb + sb2;

#pragma unroll
        for (int j = 0; j < 8; j++) {
            oa[j][0] *= ca; oa[j][1] *= ca;
            oa[j][2] *= cb; oa[j][3] *= cb;
        }
        __syncwarp();   // P visible within warp

        // ---- O += P @ V : k over 64 keys, 8 d n8-tiles ----
#pragma unroll
        for (int kk = 0; kk < 8; kk++) {
            unsigned aa[4];
            aa[0] = __float_as_uint(Pw[ra * PST + 8 * kk + q4]);
            aa[1] = __float_as_uint(Pw[(ra + 8) * PST + 8 * kk + q4]);
            aa[2] = __float_as_uint(Pw[ra * PST + 8 * kk + q4 + 4]);
            aa[3] = __float_as_uint(Pw[(ra + 8) * PST + 8 * kk + q4 + 4]);
#pragma unroll
            for (int j = 0; j < 8; j++) {
                unsigned bb[2];
                bb[0] = __float_as_uint(Vs[(8 * kk + q4) * PST + 8 * j + ra]);
                bb[1] = __float_as_uint(Vs[(8 * kk + q4 + 4) * PST + 8 * j + ra]);
                mma_tf32(oa[j], aa, bb);
            }
        }
        __syncthreads();   // done with Ks/Vs before next tile load
    }

    // ---- writeout ----
    {
        float inva = 1.f / l_a, invb = 1.f / l_b;
        const int r0 = s0 + warp * 16;
        float* dstA = out + ((size_t)(r0 + ra) * B_ + b) * D_ + h * HD_;
        float* dstB = out + ((size_t)(r0 + ra + 8) * B_ + b) * D_ + h * HD_;
#pragma unroll
        for (int j = 0; j < 8; j++) {
            *(float2*)(dstA + 8 * j + 2 * q4) =
                make_float2(oa[j][0] * inva, oa[j][1] * inva);
            *(float2*)(dstB + 8 * j + 2 * q4) =
                make_float2(oa[j][2] * invb, oa[j][3] * invb);
        }
    }
}

// ---------------------------------------------------------------------------
// out = LayerNorm(a + r) * gamma + beta
// ---------------------------------------------------------------------------
__global__ void __launch_bounds__(256)
add_ln_kernel(const float* __restrict__ a, const float* __restrict__ r,
              const float* __restrict__ gamma, const float* __restrict__ beta,
              float* __restrict__ out)
{
    const int row = blockIdx.x;
    __shared__ float buf[D_];
    __shared__ float ws[8], wq[8];
    __shared__ float red[2];
    const int tid = threadIdx.x;
    const size_t base = (size_t)row * D_;

    float s = 0.f, sq = 0.f;
    for (int i = tid; i < D_; i += 256) {
        float v = a[base + i] + r[base + i];
        buf[i] = v;
        s += v;
        sq += v * v;
    }
#pragma unroll
    for (int o = 16; o > 0; o >>= 1) {
        s  += __shfl_xor_sync(0xffffffffu, s, o);
        sq += __shfl_xor_sync(0xffffffffu, sq, o);
    }
    int lane = tid & 31, wid = tid >> 5;
    if (lane == 0) { ws[wid] = s; wq[wid] = sq; }
    __syncthreads();
    if (tid == 0) {
        float Ssum = 0.f, Q = 0.f;
#pragma unroll
        for (int w = 0; w < 8; w++) { Ssum += ws[w]; Q += wq[w]; }
        float mu  = Ssum * (1.0f / D_);
        float var = Q * (1.0f / D_) - mu * mu;
        red[0] = mu;
        red[1] = rsqrtf(var + 1e-5f);
    }
    __syncthreads();
    float mu = red[0], rstd = red[1];
    for (int i = tid; i < D_; i += 256)
        out[base + i] = (buf[i] - mu) * rstd * gamma[i] + beta[i];
}

// ---------------------------------------------------------------------------
extern "C" void kernel_launch(void* const* d_in, const int* in_sizes, int n_in,
                              void* d_out, int out_size)
{
    (void)in_sizes; (void)n_in; (void)out_size;
    const float* src  = (const float*)d_in[0];
    const float* inw  = (const float*)d_in[1];
    const float* inb  = (const float*)d_in[2];
    const float* outw = (const float*)d_in[3];
    const float* outb = (const float*)d_in[4];
    const float* g1   = (const float*)d_in[5];
    const float* be1  = (const float*)d_in[6];
    const float* g2   = (const float*)d_in[7];
    const float* be2  = (const float*)d_in[8];
    const float* w1   = (const float*)d_in[9];
    const float* b1   = (const float*)d_in[10];
    const float* w2   = (const float*)d_in[11];
    const float* b2   = (const float*)d_in[12];
    float* out = (float*)d_out;

    float *qkv, *attn, *proj, *x1, *hbuf, *moe;
    cudaGetSymbolAddress((void**)&qkv,  g_qkv);
    cudaGetSymbolAddress((void**)&attn, g_attn);
    cudaGetSymbolAddress((void**)&proj, g_proj);
    cudaGetSymbolAddress((void**)&x1,   g_x1);
    cudaGetSymbolAddress((void**)&hbuf, g_h);
    cudaGetSymbolAddress((void**)&moe,  g_moe);

    dim3 blk(256);

    // 1) qkv = src @ in_proj_w^T + b   [8192 x 3072]
    gemm_tf32<false, false><<<dim3(D3_ / 128, NTOK / 128), blk>>>(
        src, D_, inw, D_, inb, qkv, D3_, NTOK, D3_, D_, 0, 0);

    // 2) attention -> attn [8192 x 1024]  (register-resident FA2, tf32 mma)
    cudaFuncSetAttribute(attn_mma,
                         cudaFuncAttributeMaxDynamicSharedMemorySize, ATT_SMEM);
    attn_mma<<<dim3(S_ / 128, B_ * H_), blk, ATT_SMEM>>>(qkv, attn);

    // 3) proj = attn @ out_proj_w^T + b [8192 x 1024]
    gemm_tf32<false, false><<<dim3(D_ / 128, NTOK / 128), blk>>>(
        attn, D_, outw, D_, outb, proj, D_, NTOK, D_, D_, 0, 0);

    // 4) x1 = LN(src + proj)
    add_ln_kernel<<<NTOK, blk>>>(src, proj, g1, be1, x1);

    // 5) MoE: ALL experts in two batched launches (68 M-tiles total)
    gemm_tf32<true, true><<<dim3(F_ / 128, 68), blk>>>(
        x1, D_, w1, D_, b1, hbuf, F_, NTOK, F_, D_,
        (size_t)F_ * D_, F_);
    gemm_tf32<false, true><<<dim3(D_ / 128, 68), blk>>>(
        hbuf, F_, w2, F_, b2, moe, D_, NTOK, D_, F_,
        (size_t)D_ * F_, D_);

    // 6) out = LN(x1 + moe)
    add_ln_kernel<<<NTOK, blk>>>(x1, moe, g2, be2, out);
}

// round 8
// speedup vs baseline: 8.6771x; 2.5825x over previous
#include <cuda_runtime.h>
#include <mma.h>
#include <cuda_fp16.h>
#include <math.h>
#include <cstdint>

using namespace nvcuda;

#define S_  1024
#define B_  8
#define D_  1024
#define H_  16
#define HD_ 64
#define F_  4096
#define E_  8
#define NTOK (S_ * B_)      // 8192 tokens
#define D3_ (3 * D_)        // 3072

// ---------------- scratch (device globals: no allocs allowed) ----------------
__device__ float  g_qkv [(size_t)NTOK * D3_];   // fp32 for attention
__device__ float  g_proj[(size_t)NTOK * D_];
__device__ float  g_x1  [(size_t)NTOK * D_];
__device__ float  g_moe [(size_t)NTOK * D_];
__device__ __half g_srch [(size_t)NTOK * D_];
__device__ __half g_inwh [(size_t)D3_ * D_];
__device__ __half g_outwh[(size_t)D_ * D_];
__device__ __half g_w1h  [(size_t)E_ * F_ * D_];
__device__ __half g_w2h  [(size_t)E_ * D_ * F_];
__device__ __half g_attnh[(size_t)NTOK * D_];
__device__ __half g_x1h  [(size_t)NTOK * D_];
__device__ __half g_hh   [(size_t)NTOK * F_];

// ---------------------------------------------------------------------------
// PTX helpers
// ---------------------------------------------------------------------------
__device__ __forceinline__ void cp_async16(unsigned int smem_addr,
                                           const void* gptr, bool valid)
{
    int sz = valid ? 16 : 0;
    asm volatile("cp.async.cg.shared.global [%0], [%1], 16, %2;\n"
                 :: "r"(smem_addr), "l"(gptr), "r"(sz));
}
__device__ __forceinline__ void cp_commit() {
    asm volatile("cp.async.commit_group;\n");
}
__device__ __forceinline__ void cp_wait1() {
    asm volatile("cp.async.wait_group 1;\n");
}

__device__ __forceinline__ void mma_tf32(float d[4], const unsigned a[4],
                                         const unsigned b[2])
{
    asm volatile(
        "mma.sync.aligned.m16n8k8.row.col.f32.tf32.tf32.f32 "
        "{%0,%1,%2,%3}, {%4,%5,%6,%7}, {%8,%9}, {%0,%1,%2,%3};"
        : "+f"(d[0]), "+f"(d[1]), "+f"(d[2]), "+f"(d[3])
        : "r"(a[0]), "r"(a[1]), "r"(a[2]), "r"(a[3]), "r"(b[0]), "r"(b[1]));
}
__device__ __forceinline__ float tf32_rna(float x) {
    unsigned u;
    asm("cvt.rna.tf32.f32 %0, %1;" : "=r"(u) : "f"(x));
    return __uint_as_float(u);
}

// ---------------------------------------------------------------------------
// fp32 -> fp16 convert (RN), 8 elements per thread
// ---------------------------------------------------------------------------
__global__ void __launch_bounds__(256)
f2h_kernel(const float* __restrict__ in, __half* __restrict__ out, int n)
{
    int i = (blockIdx.x * 256 + threadIdx.x) * 8;
    if (i >= n) return;
    float4 a = *(const float4*)(in + i);
    float4 b = *(const float4*)(in + i + 4);
    __half2 h0 = __floats2half2_rn(a.x, a.y);
    __half2 h1 = __floats2half2_rn(a.z, a.w);
    __half2 h2 = __floats2half2_rn(b.x, b.y);
    __half2 h3 = __floats2half2_rn(b.z, b.w);
    uint4 u;
    u.x = *(unsigned*)&h0; u.y = *(unsigned*)&h1;
    u.z = *(unsigned*)&h2; u.w = *(unsigned*)&h3;
    *(uint4*)(out + i) = u;
}

// ---------------------------------------------------------------------------
// fp16 WMMA GEMM (m16n16k16), 2-stage cp.async pipeline, fp32 accumulate.
//   C[M,N] = A[M,K] @ W[N,K]^T + bias[N]   (optional ReLU, optional half out)
// Block tile 128x128, BK=32, 256 threads = 8 warps, warp tile 32x64.
// ---------------------------------------------------------------------------
#define HBK  32
#define HAST 40   // half stride (32 + 8 pad); 80 bytes/row

template<bool RELU, bool MOE, bool HOUT>
__global__ void __launch_bounds__(256, 2)
gemm_h(const __half* __restrict__ Abase, int lda,
       const __half* __restrict__ Wbase, int ldb,
       const float* __restrict__ biasbase,
       float* __restrict__ C32, __half* __restrict__ C16, int ldc,
       int M, int N, int K, size_t wstride, int bstride)
{
    __shared__ __half As[2][128][HAST];
    __shared__ __half Bs[2][128][HAST];

    const int tid  = threadIdx.x;
    const int warp = tid >> 5;
    const int lane = tid & 31;
    const int wm   = warp & 3;
    const int wn   = warp >> 2;
    const int n0   = blockIdx.x * 128;

    int m0, Mb;
    const __half* A = Abase;
    const __half* W = Wbase;
    const float* bias = biasbase;
    if (MOE) {
        const int tcnt[8] = {54, 7, 2, 1, 1, 1, 1, 1};
        const int toff[8] = {0, 6852, 7709, 7963, 8070, 8125, 8157, 8177};
        const int tn[8]   = {6852, 857, 254, 107, 55, 32, 20, 15};
        int y = blockIdx.y, e = 0, acc = 0;
        while (y >= acc + tcnt[e]) { acc += tcnt[e]; e++; }
        m0 = toff[e] + (y - acc) * 128;
        Mb = toff[e] + tn[e];
        W    = Wbase + (size_t)e * wstride;
        bias = biasbase + (size_t)e * bstride;
    } else {
        m0 = blockIdx.y * 128;
        Mb = M;
    }

    const int lrow = tid >> 2;          // 0..63
    const int lch  = tid & 3;           // 16B chunk: 8 halfs

    unsigned sA = (unsigned)__cvta_generic_to_shared(&As[0][0][0]);
    unsigned sB = (unsigned)__cvta_generic_to_shared(&Bs[0][0][0]);
    const unsigned stageBytes = 128 * HAST * 2;

    auto issue = [&](int stage, int k0) {
#pragma unroll
        for (int t = 0; t < 2; t++) {
            int row = lrow + t * 64;
            cp_async16(sA + stage * stageBytes + (row * HAST + lch * 8) * 2,
                       A + (size_t)(m0 + row) * lda + k0 + lch * 8,
                       m0 + row < Mb);
            cp_async16(sB + stage * stageBytes + (row * HAST + lch * 8) * 2,
                       W + (size_t)(n0 + row) * ldb + k0 + lch * 8,
                       n0 + row < N);
        }
    };

    wmma::fragment<wmma::accumulator, 16, 16, 16, float> accf[2][4];
#pragma unroll
    for (int i = 0; i < 2; i++)
#pragma unroll
        for (int j = 0; j < 4; j++)
            wmma::fill_fragment(accf[i][j], 0.0f);

    const int ntiles = K / HBK;
    issue(0, 0);
    cp_commit();

    for (int kt = 0; kt < ntiles; kt++) {
        int cur = kt & 1;
        if (kt + 1 < ntiles) issue(cur ^ 1, (kt + 1) * HBK);
        cp_commit();
        cp_wait1();
        __syncthreads();

#pragma unroll
        for (int kk = 0; kk < HBK; kk += 16) {
            wmma::fragment<wmma::matrix_a, 16, 16, 16, __half,
                           wmma::row_major> af[2];
            wmma::fragment<wmma::matrix_b, 16, 16, 16, __half,
                           wmma::col_major> bf[4];
#pragma unroll
            for (int i = 0; i < 2; i++)
                wmma::load_matrix_sync(af[i], &As[cur][wm * 32 + i * 16][kk],
                                       HAST);
#pragma unroll
            for (int j = 0; j < 4; j++)
                wmma::load_matrix_sync(bf[j], &Bs[cur][wn * 64 + j * 16][kk],
                                       HAST);
#pragma unroll
            for (int i = 0; i < 2; i++)
#pragma unroll
                for (int j = 0; j < 4; j++)
                    wmma::mma_sync(accf[i][j], af[i], bf[j], accf[i][j]);
        }
        __syncthreads();
    }

    // epilogue: stage 16x16 fragments through smem; lane owns 8 consecutive cols
    __syncthreads();
    float* sb = (float*)&As[0][0][0] + warp * 256;
    const int er = lane >> 1;            // row 0..15
    const int ec = (lane & 1) * 8;       // col base 0 or 8
#pragma unroll
    for (int i = 0; i < 2; i++) {
#pragma unroll
        for (int j = 0; j < 4; j++) {
            wmma::store_matrix_sync(sb, accf[i][j], 16, wmma::mem_row_major);
            __syncwarp();
            int r = m0 + wm * 32 + i * 16 + er;
            int c = n0 + wn * 64 + j * 16 + ec;
            if (r < Mb) {
                float v[8];
#pragma unroll
                for (int q = 0; q < 8; q++) {
                    v[q] = sb[er * 16 + ec + q] + bias[c + q];
                    if (RELU) v[q] = fmaxf(v[q], 0.f);
                }
                if (HOUT) {
                    __half2 h0 = __floats2half2_rn(v[0], v[1]);
                    __half2 h1 = __floats2half2_rn(v[2], v[3]);
                    __half2 h2 = __floats2half2_rn(v[4], v[5]);
                    __half2 h3 = __floats2half2_rn(v[6], v[7]);
                    uint4 u;
                    u.x = *(unsigned*)&h0; u.y = *(unsigned*)&h1;
                    u.z = *(unsigned*)&h2; u.w = *(unsigned*)&h3;
                    *(uint4*)(C16 + (size_t)r * ldc + c) = u;
                } else {
                    *(float4*)(C32 + (size_t)r * ldc + c) =
                        make_float4(v[0], v[1], v[2], v[3]);
                    *(float4*)(C32 + (size_t)r * ldc + c + 4) =
                        make_float4(v[4], v[5], v[6], v[7]);
                }
            }
            __syncwarp();
        }
    }
}

// ---------------------------------------------------------------------------
// Flash attention, register-resident FA2, tf32 mma (R6), fp16 output.
// ---------------------------------------------------------------------------
#define PST 68
#define ATT_SMEM ((2 * 64 * PST + 8 * 16 * PST) * 4)   // 69632 bytes

__global__ void __launch_bounds__(256)
attn_mma(const float* __restrict__ qkv, __half* __restrict__ out)
{
    extern __shared__ float sm[];
    float* Ks = sm;
    float* Vs = Ks + 64 * PST;
    float* Ps = Vs + 64 * PST;

    const int tid  = threadIdx.x;
    const int warp = tid >> 5, lane = tid & 31;
    const int ra = lane >> 2, q4 = lane & 3;
    const int s0 = blockIdx.x * 128;
    const int b  = blockIdx.y >> 4, h = blockIdx.y & 15;
    float* Pw = Ps + warp * 16 * PST;

    unsigned qa[8][4];
    {
        const int r0 = s0 + warp * 16;
        const float* rowA = qkv + ((size_t)(r0 + ra) * B_ + b) * D3_ + h * HD_;
        const float* rowB = qkv + ((size_t)(r0 + ra + 8) * B_ + b) * D3_ + h * HD_;
#pragma unroll
        for (int j = 0; j < 8; j++) {
            qa[j][0] = __float_as_uint(rowA[8 * j + q4] * 0.125f);
            qa[j][1] = __float_as_uint(rowB[8 * j + q4] * 0.125f);
            qa[j][2] = __float_as_uint(rowA[8 * j + q4 + 4] * 0.125f);
            qa[j][3] = __float_as_uint(rowB[8 * j + q4 + 4] * 0.125f);
        }
    }

    float oa[8][4];
#pragma unroll
    for (int j = 0; j < 8; j++)
#pragma unroll
        for (int e = 0; e < 4; e++) oa[j][e] = 0.f;
    float m_a = -1e30f, m_b = -1e30f, l_a = 0.f, l_b = 0.f;

    for (int t0 = 0; t0 < S_; t0 += 64) {
#pragma unroll
        for (int it = 0; it < 4; it++) {
            int i  = tid + it * 256;
            int rr = i >> 4;
            int c4 = (i & 15) << 2;
            size_t base = ((size_t)(t0 + rr) * B_ + b) * D3_ + h * HD_ + c4;
            *(float4*)(Ks + rr * PST + c4) = *(const float4*)(qkv + base + D_);
            *(float4*)(Vs + rr * PST + c4) = *(const float4*)(qkv + base + 2 * D_);
        }
        __syncthreads();

        float sacc[8][4];
#pragma unroll
        for (int j = 0; j < 8; j++)
#pragma unroll
            for (int e = 0; e < 4; e++) sacc[j][e] = 0.f;
#pragma unroll
        for (int kk = 0; kk < 8; kk++) {
#pragma unroll
            for (int j = 0; j < 8; j++) {
                unsigned bb[2];
                const float* kr = Ks + (8 * j + ra) * PST + 8 * kk + q4;
                bb[0] = __float_as_uint(kr[0]);
                bb[1] = __float_as_uint(kr[4]);
                mma_tf32(sacc[j], qa[kk], bb);
            }
        }

        float mxa = sacc[0][0], mxb = sacc[0][2];
#pragma unroll
        for (int j = 0; j < 8; j++) {
            mxa = fmaxf(mxa, fmaxf(sacc[j][0], sacc[j][1]));
            mxb = fmaxf(mxb, fmaxf(sacc[j][2], sacc[j][3]));
        }
        mxa = fmaxf(mxa, __shfl_xor_sync(0xffffffffu, mxa, 1));
        mxa = fmaxf(mxa, __shfl_xor_sync(0xffffffffu, mxa, 2));
        mxb = fmaxf(mxb, __shfl_xor_sync(0xffffffffu, mxb, 1));
        mxb = fmaxf(mxb, __shfl_xor_sync(0xffffffffu, mxb, 2));

        float mna = fmaxf(m_a, mxa), mnb = fmaxf(m_b, mxb);
        float ca = __expf(m_a - mna), cb = __expf(m_b - mnb);
        m_a = mna; m_b = mnb;

        float sa = 0.f, sb2 = 0.f;
#pragma unroll
        for (int j = 0; j < 8; j++) {
            float p0 = tf32_rna(__expf(sacc[j][0] - mna));
            float p1 = tf32_rna(__expf(sacc[j][1] - mna));
            float p2 = tf32_rna(__expf(sacc[j][2] - mnb));
            float p3 = tf32_rna(__expf(sacc[j][3] - mnb));
            sa  += p0 + p1;
            sb2 += p2 + p3;
            *(float2*)(Pw + ra * PST + 8 * j + 2 * q4)       = make_float2(p0, p1);
            *(float2*)(Pw + (ra + 8) * PST + 8 * j + 2 * q4) = make_float2(p2, p3);
        }
        sa  += __shfl_xor_sync(0xffffffffu, sa, 1);
        sa  += __shfl_xor_sync(0xffffffffu, sa, 2);
        sb2 += __shfl_xor_sync(0xffffffffu, sb2, 1);
        sb2 += __shfl_xor_sync(0xffffffffu, sb2, 2);
        l_a = l_a * ca + sa;
        l_b = l_b * cb + sb2;

#pragma unroll
        for (int j = 0; j < 8; j++) {
            oa[j][0] *= ca; oa[j][1] *= ca;
            oa[j][2] *= cb; oa[j][3] *= cb;
        }
        __syncwarp();

#pragma unroll
        for (int kk = 0; kk < 8; kk++) {
            unsigned aa[4];
            aa[0] = __float_as_uint(Pw[ra * PST + 8 * kk + q4]);
            aa[1] = __float_as_uint(Pw[(ra + 8) * PST + 8 * kk + q4]);
            aa[2] = __float_as_uint(Pw[ra * PST + 8 * kk + q4 + 4]);
            aa[3] = __float_as_uint(Pw[(ra + 8) * PST + 8 * kk + q4 + 4]);
#pragma unroll
            for (int j = 0; j < 8; j++) {
                unsigned bb[2];
                bb[0] = __float_as_uint(Vs[(8 * kk + q4) * PST + 8 * j + ra]);
                bb[1] = __float_as_uint(Vs[(8 * kk + q4 + 4) * PST + 8 * j + ra]);
                mma_tf32(oa[j], aa, bb);
            }
        }
        __syncthreads();
    }

    {
        float inva = 1.f / l_a, invb = 1.f / l_b;
        const int r0 = s0 + warp * 16;
        __half* dstA = out + ((size_t)(r0 + ra) * B_ + b) * D_ + h * HD_;
        __half* dstB = out + ((size_t)(r0 + ra + 8) * B_ + b) * D_ + h * HD_;
#pragma unroll
        for (int j = 0; j < 8; j++) {
            __half2 ha = __floats2half2_rn(oa[j][0] * inva, oa[j][1] * inva);
            __half2 hb = __floats2half2_rn(oa[j][2] * invb, oa[j][3] * invb);
            *(__half2*)(dstA + 8 * j + 2 * q4) = ha;
            *(__half2*)(dstB + 8 * j + 2 * q4) = hb;
        }
    }
}

// ---------------------------------------------------------------------------
// out = LayerNorm(a + r) * gamma + beta   (+ optional fp16 copy)
// ---------------------------------------------------------------------------
template<bool HOUT>
__global__ void __launch_bounds__(256)
add_ln_kernel(const float* __restrict__ a, const float* __restrict__ r,
              const float* __restrict__ gamma, const float* __restrict__ beta,
              float* __restrict__ out, __half* __restrict__ outh)
{
    const int row = blockIdx.x;
    __shared__ float buf[D_];
    __shared__ float ws[8], wq[8];
    __shared__ float red[2];
    const int tid = threadIdx.x;
    const size_t base = (size_t)row * D_;

    float s = 0.f, sq = 0.f;
    for (int i = tid; i < D_; i += 256) {
        float v = a[base + i] + r[base + i];
        buf[i] = v;
        s += v;
        sq += v * v;
    }
#pragma unroll
    for (int o = 16; o > 0; o >>= 1) {
        s  += __shfl_xor_sync(0xffffffffu, s, o);
        sq += __shfl_xor_sync(0xffffffffu, sq, o);
    }
    int lane = tid & 31, wid = tid >> 5;
    if (lane == 0) { ws[wid] = s; wq[wid] = sq; }
    __syncthreads();
    if (tid == 0) {
        float Ssum = 0.f, Q = 0.f;
#pragma unroll
        for (int w = 0; w < 8; w++) { Ssum += ws[w]; Q += wq[w]; }
        float mu  = Ssum * (1.0f / D_);
        float var = Q * (1.0f / D_) - mu * mu;
        red[0] = mu;
        red[1] = rsqrtf(var + 1e-5f);
    }
    __syncthreads();
    float mu = red[0], rstd = red[1];
    for (int i = tid; i < D_; i += 256) {
        float v = (buf[i] - mu) * rstd * gamma[i] + beta[i];
        out[base + i] = v;
        if (HOUT) outh[base + i] = __float2half_rn(v);
    }
}

// ---------------------------------------------------------------------------
extern "C" void kernel_launch(void* const* d_in, const int* in_sizes, int n_in,
                              void* d_out, int out_size)
{
    (void)in_sizes; (void)n_in; (void)out_size;
    const float* src  = (const float*)d_in[0];
    const float* inw  = (const float*)d_in[1];
    const float* inb  = (const float*)d_in[2];
    const float* outw = (const float*)d_in[3];
    const float* outb = (const float*)d_in[4];
    const float* g1   = (const float*)d_in[5];
    const float* be1  = (const float*)d_in[6];
    const float* g2   = (const float*)d_in[7];
    const float* be2  = (const float*)d_in[8];
    const float* w1   = (const float*)d_in[9];
    const float* b1   = (const float*)d_in[10];
    const float* w2   = (const float*)d_in[11];
    const float* b2   = (const float*)d_in[12];
    float* out = (float*)d_out;

    float  *qkv, *proj, *x1, *moe;
    __half *srch, *inwh, *outwh, *w1h, *w2h, *attnh, *x1h, *hh;
    cudaGetSymbolAddress((void**)&qkv,   g_qkv);
    cudaGetSymbolAddress((void**)&proj,  g_proj);
    cudaGetSymbolAddress((void**)&x1,    g_x1);
    cudaGetSymbolAddress((void**)&moe,   g_moe);
    cudaGetSymbolAddress((void**)&srch,  g_srch);
    cudaGetSymbolAddress((void**)&inwh,  g_inwh);
    cudaGetSymbolAddress((void**)&outwh, g_outwh);
    cudaGetSymbolAddress((void**)&w1h,   g_w1h);
    cudaGetSymbolAddress((void**)&w2h,   g_w2h);
    cudaGetSymbolAddress((void**)&attnh, g_attnh);
    cudaGetSymbolAddress((void**)&x1h,   g_x1h);
    cudaGetSymbolAddress((void**)&hh,    g_hh);

    cudaFuncSetAttribute(attn_mma,
                         cudaFuncAttributeMaxDynamicSharedMemorySize, ATT_SMEM);

    dim3 blk(256);

    // 0) fp16 conversions (weights + src)
    f2h_kernel<<<(NTOK * D_) / 2048, blk>>>(src, srch, NTOK * D_);
    f2h_kernel<<<(D3_ * D_) / 2048, blk>>>(inw, inwh, D3_ * D_);
    f2h_kernel<<<(D_ * D_) / 2048, blk>>>(outw, outwh, D_ * D_);
    f2h_kernel<<<(E_ * F_ * D_) / 2048, blk>>>(w1, w1h, E_ * F_ * D_);
    f2h_kernel<<<(E_ * D_ * F_) / 2048, blk>>>(w2, w2h, E_ * D_ * F_);

    // 1) qkv = src @ in_proj_w^T + b   [8192 x 3072], fp32 out
    gemm_h<false, false, false><<<dim3(D3_ / 128, NTOK / 128), blk>>>(
        srch, D_, inwh, D_, inb, qkv, nullptr, D3_, NTOK, D3_, D_, 0, 0);

    // 2) attention -> attnh [8192 x 1024] (fp16 out)
    attn_mma<<<dim3(S_ / 128, B_ * H_), blk, ATT_SMEM>>>(qkv, attnh);

    // 3) proj = attn @ out_proj_w^T + b [8192 x 1024], fp32 out
    gemm_h<false, false, false><<<dim3(D_ / 128, NTOK / 128), blk>>>(
        attnh, D_, outwh, D_, outb, proj, nullptr, D_, NTOK, D_, D_, 0, 0);

    // 4) x1 = LN(src + proj)  (fp32 + fp16 copies)
    add_ln_kernel<true><<<NTOK, blk>>>(src, proj, g1, be1, x1, x1h);

    // 5) MoE: batched expert GEMMs; h stays fp16
    gemm_h<true, true, true><<<dim3(F_ / 128, 68), blk>>>(
        x1h, D_, w1h, D_, b1, nullptr, hh, F_, NTOK, F_, D_,
        (size_t)F_ * D_, F_);
    gemm_h<false, true, false><<<dim3(D_ / 128, 68), blk>>>(
        hh, F_, w2h, F_, b2, moe, nullptr, D_, NTOK, D_, F_,
        (size_t)D_ * F_, D_);

    // 6) out = LN(x1 + moe)
    add_ln_kernel<false><<<NTOK, blk>>>(x1, moe, g2, be2, out, nullptr);
}

// round 9
// speedup vs baseline: 9.6822x; 1.1158x over previous
#include <cuda_runtime.h>
#include <mma.h>
#include <cuda_fp16.h>
#include <math.h>
#include <cstdint>

using namespace nvcuda;

#define S_  1024
#define B_  8
#define D_  1024
#define H_  16
#define HD_ 64
#define F_  4096
#define E_  8
#define NTOK (S_ * B_)      // 8192 tokens
#define D3_ (3 * D_)        // 3072

// ---------------- scratch (device globals: no allocs allowed) ----------------
__device__ __half g_qkvh [(size_t)NTOK * D3_];
__device__ float  g_proj[(size_t)NTOK * D_];
__device__ float  g_x1  [(size_t)NTOK * D_];
__device__ float  g_moe [(size_t)NTOK * D_];
__device__ __half g_srch [(size_t)NTOK * D_];
__device__ __half g_inwh [(size_t)D3_ * D_];
__device__ __half g_outwh[(size_t)D_ * D_];
__device__ __half g_w1h  [(size_t)E_ * F_ * D_];
__device__ __half g_w2h  [(size_t)E_ * D_ * F_];
__device__ __half g_attnh[(size_t)NTOK * D_];
__device__ __half g_x1h  [(size_t)NTOK * D_];
__device__ __half g_hh   [(size_t)NTOK * F_];

// ---------------------------------------------------------------------------
// PTX helpers
// ---------------------------------------------------------------------------
__device__ __forceinline__ void cp_async16(unsigned int smem_addr,
                                           const void* gptr, bool valid)
{
    int sz = valid ? 16 : 0;
    asm volatile("cp.async.cg.shared.global [%0], [%1], 16, %2;\n"
                 :: "r"(smem_addr), "l"(gptr), "r"(sz));
}
__device__ __forceinline__ void cp_commit() {
    asm volatile("cp.async.commit_group;\n");
}
__device__ __forceinline__ void cp_wait1() {
    asm volatile("cp.async.wait_group 1;\n");
}

// fp16 mma m16n8k16, fp32 accumulate in place
__device__ __forceinline__ void mma_h16(float d[4], const unsigned a[4],
                                        const unsigned b[2])
{
    asm volatile(
        "mma.sync.aligned.m16n8k16.row.col.f32.f16.f16.f32 "
        "{%0,%1,%2,%3}, {%4,%5,%6,%7}, {%8,%9}, {%0,%1,%2,%3};"
        : "+f"(d[0]), "+f"(d[1]), "+f"(d[2]), "+f"(d[3])
        : "r"(a[0]), "r"(a[1]), "r"(a[2]), "r"(a[3]), "r"(b[0]), "r"(b[1]));
}

// ---------------------------------------------------------------------------
// fp32 -> fp16 convert (RN), 8 elements per thread
// ---------------------------------------------------------------------------
__global__ void __launch_bounds__(256)
f2h_kernel(const float* __restrict__ in, __half* __restrict__ out, int n)
{
    int i = (blockIdx.x * 256 + threadIdx.x) * 8;
    if (i >= n) return;
    float4 a = *(const float4*)(in + i);
    float4 b = *(const float4*)(in + i + 4);
    __half2 h0 = __floats2half2_rn(a.x, a.y);
    __half2 h1 = __floats2half2_rn(a.z, a.w);
    __half2 h2 = __floats2half2_rn(b.x, b.y);
    __half2 h3 = __floats2half2_rn(b.z, b.w);
    uint4 u;
    u.x = *(unsigned*)&h0; u.y = *(unsigned*)&h1;
    u.z = *(unsigned*)&h2; u.w = *(unsigned*)&h3;
    *(uint4*)(out + i) = u;
}

// ---------------------------------------------------------------------------
// fp16 WMMA GEMM (m16n16k16), 2-stage cp.async pipeline, fp32 accumulate.
//   C[M,N] = A[M,K] @ W[N,K]^T + bias[N]   (optional ReLU, optional half out)
// Block tile 128x128, BK=32, 256 threads = 8 warps, warp tile 32x64.
// ---------------------------------------------------------------------------
#define HBK  32
#define HAST 40   // half stride (32 + 8 pad); 80 bytes/row

template<bool RELU, bool MOE, bool HOUT>
__global__ void __launch_bounds__(256, 2)
gemm_h(const __half* __restrict__ Abase, int lda,
       const __half* __restrict__ Wbase, int ldb,
       const float* __restrict__ biasbase,
       float* __restrict__ C32, __half* __restrict__ C16, int ldc,
       int M, int N, int K, size_t wstride, int bstride)
{
    __shared__ __half As[2][128][HAST];
    __shared__ __half Bs[2][128][HAST];

    const int tid  = threadIdx.x;
    const int warp = tid >> 5;
    const int lane = tid & 31;
    const int wm   = warp & 3;
    const int wn   = warp >> 2;
    const int n0   = blockIdx.x * 128;

    int m0, Mb;
    const __half* A = Abase;
    const __half* W = Wbase;
    const float* bias = biasbase;
    if (MOE) {
        const int tcnt[8] = {54, 7, 2, 1, 1, 1, 1, 1};
        const int toff[8] = {0, 6852, 7709, 7963, 8070, 8125, 8157, 8177};
        const int tn[8]   = {6852, 857, 254, 107, 55, 32, 20, 15};
        int y = blockIdx.y, e = 0, acc = 0;
        while (y >= acc + tcnt[e]) { acc += tcnt[e]; e++; }
        m0 = toff[e] + (y - acc) * 128;
        Mb = toff[e] + tn[e];
        W    = Wbase + (size_t)e * wstride;
        bias = biasbase + (size_t)e * bstride;
    } else {
        m0 = blockIdx.y * 128;
        Mb = M;
    }

    const int lrow = tid >> 2;          // 0..63
    const int lch  = tid & 3;           // 16B chunk: 8 halfs

    unsigned sA = (unsigned)__cvta_generic_to_shared(&As[0][0][0]);
    unsigned sB = (unsigned)__cvta_generic_to_shared(&Bs[0][0][0]);
    const unsigned stageBytes = 128 * HAST * 2;

    auto issue = [&](int stage, int k0) {
#pragma unroll
        for (int t = 0; t < 2; t++) {
            int row = lrow + t * 64;
            cp_async16(sA + stage * stageBytes + (row * HAST + lch * 8) * 2,
                       A + (size_t)(m0 + row) * lda + k0 + lch * 8,
                       m0 + row < Mb);
            cp_async16(sB + stage * stageBytes + (row * HAST + lch * 8) * 2,
                       W + (size_t)(n0 + row) * ldb + k0 + lch * 8,
                       n0 + row < N);
        }
    };

    wmma::fragment<wmma::accumulator, 16, 16, 16, float> accf[2][4];
#pragma unroll
    for (int i = 0; i < 2; i++)
#pragma unroll
        for (int j = 0; j < 4; j++)
            wmma::fill_fragment(accf[i][j], 0.0f);

    const int ntiles = K / HBK;
    issue(0, 0);
    cp_commit();

    for (int kt = 0; kt < ntiles; kt++) {
        int cur = kt & 1;
        if (kt + 1 < ntiles) issue(cur ^ 1, (kt + 1) * HBK);
        cp_commit();
        cp_wait1();
        __syncthreads();

#pragma unroll
        for (int kk = 0; kk < HBK; kk += 16) {
            wmma::fragment<wmma::matrix_a, 16, 16, 16, __half,
                           wmma::row_major> af[2];
            wmma::fragment<wmma::matrix_b, 16, 16, 16, __half,
                           wmma::col_major> bf[4];
#pragma unroll
            for (int i = 0; i < 2; i++)
                wmma::load_matrix_sync(af[i], &As[cur][wm * 32 + i * 16][kk],
                                       HAST);
#pragma unroll
            for (int j = 0; j < 4; j++)
                wmma::load_matrix_sync(bf[j], &Bs[cur][wn * 64 + j * 16][kk],
                                       HAST);
#pragma unroll
            for (int i = 0; i < 2; i++)
#pragma unroll
                for (int j = 0; j < 4; j++)
                    wmma::mma_sync(accf[i][j], af[i], bf[j], accf[i][j]);
        }
        __syncthreads();
    }

    // epilogue: stage 16x16 fragments through smem; lane owns 8 consecutive cols
    __syncthreads();
    float* sb = (float*)&As[0][0][0] + warp * 256;
    const int er = lane >> 1;            // row 0..15
    const int ec = (lane & 1) * 8;       // col base 0 or 8
#pragma unroll
    for (int i = 0; i < 2; i++) {
#pragma unroll
        for (int j = 0; j < 4; j++) {
            wmma::store_matrix_sync(sb, accf[i][j], 16, wmma::mem_row_major);
            __syncwarp();
            int r = m0 + wm * 32 + i * 16 + er;
            int c = n0 + wn * 64 + j * 16 + ec;
            if (r < Mb) {
                float v[8];
#pragma unroll
                for (int q = 0; q < 8; q++) {
                    v[q] = sb[er * 16 + ec + q] + bias[c + q];
                    if (RELU) v[q] = fmaxf(v[q], 0.f);
                }
                if (HOUT) {
                    __half2 h0 = __floats2half2_rn(v[0], v[1]);
                    __half2 h1 = __floats2half2_rn(v[2], v[3]);
                    __half2 h2 = __floats2half2_rn(v[4], v[5]);
                    __half2 h3 = __floats2half2_rn(v[6], v[7]);
                    uint4 u;
                    u.x = *(unsigned*)&h0; u.y = *(unsigned*)&h1;
                    u.z = *(unsigned*)&h2; u.w = *(unsigned*)&h3;
                    *(uint4*)(C16 + (size_t)r * ldc + c) = u;
                } else {
                    *(float4*)(C32 + (size_t)r * ldc + c) =
                        make_float4(v[0], v[1], v[2], v[3]);
                    *(float4*)(C32 + (size_t)r * ldc + c + 4) =
                        make_float4(v[4], v[5], v[6], v[7]);
                }
            }
            __syncwarp();
        }
    }
}

// ---------------------------------------------------------------------------
// Flash attention, register-resident FA2, fp16 mma.m16n8k16.
// CTA = 128 queries x one (b,h) head; 8 warps x 16 query rows.
// Q in packed half2 a-frags (loaded once, x0.125 exact). K row-major smem;
// V stored TRANSPOSED (Vt[d][key]) so PV b-frags are contiguous half2.
// S/O accumulate fp32; P rounded to fp16 (l summed from rounded values).
//
// m16n8k16 layouts (ra = lane>>2, q4 = lane&3):
//   A: a0=(r=ra, k=2q4..+1) a1=(r=ra+8,same) a2=(r=ra,k=2q4+8..+9) a3=(ra+8)
//   B: b0=(k=2q4..+1, n=ra) b1=(k=2q4+8..+9, n=ra)
//   C: c0=(r=ra,c=2q4) c1=(+1) c2=(r=ra+8,c=2q4) c3=(+1)
// ---------------------------------------------------------------------------
#define KST 72   // half stride for K/Vt/P rows

__global__ void __launch_bounds__(256)
attn_h(const __half* __restrict__ qkv, __half* __restrict__ out)
{
    __shared__ __half Ks[64 * KST];          // [key][d]
    __shared__ __half Vt[64 * KST];          // [d][key]
    __shared__ __half Ps[8 * 16 * KST];      // per-warp [row][key]

    const int tid  = threadIdx.x;
    const int warp = tid >> 5, lane = tid & 31;
    const int ra = lane >> 2, q4 = lane & 3;
    const int s0 = blockIdx.x * 128;
    const int b  = blockIdx.y >> 4, h = blockIdx.y & 15;
    __half* Pw = Ps + warp * 16 * KST;

    // ---- Q a-fragments (half2-packed, scaled by exact 0.125) ----
    unsigned qa[4][4];
    {
        const __half2 sc = __half2half2(__float2half(0.125f));
        const int r0 = s0 + warp * 16;
        const __half* rowA = qkv + ((size_t)(r0 + ra) * B_ + b) * D3_ + h * HD_;
        const __half* rowB = qkv + ((size_t)(r0 + ra + 8) * B_ + b) * D3_ + h * HD_;
#pragma unroll
        for (int kk = 0; kk < 4; kk++) {
            __half2 v;
            v = __hmul2(*(const __half2*)(rowA + 16 * kk + 2 * q4), sc);
            qa[kk][0] = *(unsigned*)&v;
            v = __hmul2(*(const __half2*)(rowB + 16 * kk + 2 * q4), sc);
            qa[kk][1] = *(unsigned*)&v;
            v = __hmul2(*(const __half2*)(rowA + 16 * kk + 2 * q4 + 8), sc);
            qa[kk][2] = *(unsigned*)&v;
            v = __hmul2(*(const __half2*)(rowB + 16 * kk + 2 * q4 + 8), sc);
            qa[kk][3] = *(unsigned*)&v;
        }
    }

    float oa[8][4];
#pragma unroll
    for (int j = 0; j < 8; j++)
#pragma unroll
        for (int e = 0; e < 4; e++) oa[j][e] = 0.f;
    float m_a = -1e30f, m_b = -1e30f, l_a = 0.f, l_b = 0.f;

    for (int t0 = 0; t0 < S_; t0 += 64) {
        // ---- K direct copy; V transposed into Vt ----
#pragma unroll
        for (int it = 0; it < 2; it++) {
            int i   = tid + it * 256;        // 0..511
            int key = i >> 3;
            int d8  = (i & 7) * 8;
            size_t base = ((size_t)(t0 + key) * B_ + b) * D3_ + h * HD_ + d8;
            *(uint4*)(Ks + key * KST + d8) = *(const uint4*)(qkv + base + D_);
            uint4 vv = *(const uint4*)(qkv + base + 2 * D_);
            const __half* vh = (const __half*)&vv;
#pragma unroll
            for (int q = 0; q < 8; q++)
                Vt[(d8 + q) * KST + key] = vh[q];
        }
        __syncthreads();

        // ---- S = Q @ K^T : 8 key n8-tiles x 4 k16-steps ----
        float sacc[8][4];
#pragma unroll
        for (int j = 0; j < 8; j++)
#pragma unroll
            for (int e = 0; e < 4; e++) sacc[j][e] = 0.f;
#pragma unroll
        for (int kk = 0; kk < 4; kk++) {
#pragma unroll
            for (int j = 0; j < 8; j++) {
                unsigned bb[2];
                const __half* kr = Ks + (8 * j + ra) * KST + 16 * kk + 2 * q4;
                bb[0] = *(const unsigned*)(kr);
                bb[1] = *(const unsigned*)(kr + 8);
                mma_h16(sacc[j], qa[kk], bb);
            }
        }

        // ---- online softmax (registers; quad shfl) ----
        float mxa = sacc[0][0], mxb = sacc[0][2];
#pragma unroll
        for (int j = 0; j < 8; j++) {
            mxa = fmaxf(mxa, fmaxf(sacc[j][0], sacc[j][1]));
            mxb = fmaxf(mxb, fmaxf(sacc[j][2], sacc[j][3]));
        }
        mxa = fmaxf(mxa, __shfl_xor_sync(0xffffffffu, mxa, 1));
        mxa = fmaxf(mxa, __shfl_xor_sync(0xffffffffu, mxa, 2));
        mxb = fmaxf(mxb, __shfl_xor_sync(0xffffffffu, mxb, 1));
        mxb = fmaxf(mxb, __shfl_xor_sync(0xffffffffu, mxb, 2));

        float mna = fmaxf(m_a, mxa), mnb = fmaxf(m_b, mxb);
        float ca = __expf(m_a - mna), cb = __expf(m_b - mnb);
        m_a = mna; m_b = mnb;

        float sa = 0.f, sb2 = 0.f;
#pragma unroll
        for (int j = 0; j < 8; j++) {
            __half2 pA = __floats2half2_rn(__expf(sacc[j][0] - mna),
                                           __expf(sacc[j][1] - mna));
            __half2 pB = __floats2half2_rn(__expf(sacc[j][2] - mnb),
                                           __expf(sacc[j][3] - mnb));
            float2 fA = __half22float2(pA);
            float2 fB = __half22float2(pB);
            sa  += fA.x + fA.y;
            sb2 += fB.x + fB.y;
            *(__half2*)(Pw + ra * KST + 8 * j + 2 * q4)       = pA;
            *(__half2*)(Pw + (ra + 8) * KST + 8 * j + 2 * q4) = pB;
        }
        sa  += __shfl_xor_sync(0xffffffffu, sa, 1);
        sa  += __shfl_xor_sync(0xffffffffu, sa, 2);
        sb2 += __shfl_xor_sync(0xffffffffu, sb2, 1);
        sb2 += __shfl_xor_sync(0xffffffffu, sb2, 2);
        l_a = l_a * ca + sa;
        l_b = l_b * cb + sb2;

#pragma unroll
        for (int j = 0; j < 8; j++) {
            oa[j][0] *= ca; oa[j][1] *= ca;
            oa[j][2] *= cb; oa[j][3] *= cb;
        }
        __syncwarp();

        // ---- O += P @ V : 4 k16-steps x 8 d n8-tiles ----
#pragma unroll
        for (int kk = 0; kk < 4; kk++) {
            unsigned aa[4];
            aa[0] = *(const unsigned*)(Pw + ra * KST + 16 * kk + 2 * q4);
            aa[1] = *(const unsigned*)(Pw + (ra + 8) * KST + 16 * kk + 2 * q4);
            aa[2] = *(const unsigned*)(Pw + ra * KST + 16 * kk + 2 * q4 + 8);
            aa[3] = *(const unsigned*)(Pw + (ra + 8) * KST + 16 * kk + 2 * q4 + 8);
#pragma unroll
            for (int j = 0; j < 8; j++) {
                unsigned bb[2];
                const __half* vr = Vt + (8 * j + ra) * KST + 16 * kk + 2 * q4;
                bb[0] = *(const unsigned*)(vr);
                bb[1] = *(const unsigned*)(vr + 8);
                mma_h16(oa[j], aa, bb);
            }
        }
        __syncthreads();
    }

    // ---- writeout (fp16) ----
    {
        float inva = 1.f / l_a, invb = 1.f / l_b;
        const int r0 = s0 + warp * 16;
        __half* dstA = out + ((size_t)(r0 + ra) * B_ + b) * D_ + h * HD_;
        __half* dstB = out + ((size_t)(r0 + ra + 8) * B_ + b) * D_ + h * HD_;
#pragma unroll
        for (int j = 0; j < 8; j++) {
            *(__half2*)(dstA + 8 * j + 2 * q4) =
                __floats2half2_rn(oa[j][0] * inva, oa[j][1] * inva);
            *(__half2*)(dstB + 8 * j + 2 * q4) =
                __floats2half2_rn(oa[j][2] * invb, oa[j][3] * invb);
        }
    }
}

// ---------------------------------------------------------------------------
// out = LayerNorm(a + r) * gamma + beta   (+ optional fp16 copy)
// ---------------------------------------------------------------------------
template<bool HOUT>
__global__ void __launch_bounds__(256)
add_ln_kernel(const float* __restrict__ a, const float* __restrict__ r,
              const float* __restrict__ gamma, const float* __restrict__ beta,
              float* __restrict__ out, __half* __restrict__ outh)
{
    const int row = blockIdx.x;
    __shared__ float buf[D_];
    __shared__ float ws[8], wq[8];
    __shared__ float red[2];
    const int tid = threadIdx.x;
    const size_t base = (size_t)row * D_;

    float s = 0.f, sq = 0.f;
    for (int i = tid; i < D_; i += 256) {
        float v = a[base + i] + r[base + i];
        buf[i] = v;
        s += v;
        sq += v * v;
    }
#pragma unroll
    for (int o = 16; o > 0; o >>= 1) {
        s  += __shfl_xor_sync(0xffffffffu, s, o);
        sq += __shfl_xor_sync(0xffffffffu, sq, o);
    }
    int lane = tid & 31, wid = tid >> 5;
    if (lane == 0) { ws[wid] = s; wq[wid] = sq; }
    __syncthreads();
    if (tid == 0) {
        float Ssum = 0.f, Q = 0.f;
#pragma unroll
        for (int w = 0; w < 8; w++) { Ssum += ws[w]; Q += wq[w]; }
        float mu  = Ssum * (1.0f / D_);
        float var = Q * (1.0f / D_) - mu * mu;
        red[0] = mu;
        red[1] = rsqrtf(var + 1e-5f);
    }
    __syncthreads();
    float mu = red[0], rstd = red[1];
    for (int i = tid; i < D_; i += 256) {
        float v = (buf[i] - mu) * rstd * gamma[i] + beta[i];
        out[base + i] = v;
        if (HOUT) outh[base + i] = __float2half_rn(v);
    }
}

// ---------------------------------------------------------------------------
extern "C" void kernel_launch(void* const* d_in, const int* in_sizes, int n_in,
                              void* d_out, int out_size)
{
    (void)in_sizes; (void)n_in; (void)out_size;
    const float* src  = (const float*)d_in[0];
    const float* inw  = (const float*)d_in[1];
    const float* inb  = (const float*)d_in[2];
    const float* outw = (const float*)d_in[3];
    const float* outb = (const float*)d_in[4];
    const float* g1   = (const float*)d_in[5];
    const float* be1  = (const float*)d_in[6];
    const float* g2   = (const float*)d_in[7];
    const float* be2  = (const float*)d_in[8];
    const float* w1   = (const float*)d_in[9];
    const float* b1   = (const float*)d_in[10];
    const float* w2   = (const float*)d_in[11];
    const float* b2   = (const float*)d_in[12];
    float* out = (float*)d_out;

    float  *proj, *x1, *moe;
    __half *qkvh, *srch, *inwh, *outwh, *w1h, *w2h, *attnh, *x1h, *hh;
    cudaGetSymbolAddress((void**)&qkvh,  g_qkvh);
    cudaGetSymbolAddress((void**)&proj,  g_proj);
    cudaGetSymbolAddress((void**)&x1,    g_x1);
    cudaGetSymbolAddress((void**)&moe,   g_moe);
    cudaGetSymbolAddress((void**)&srch,  g_srch);
    cudaGetSymbolAddress((void**)&inwh,  g_inwh);
    cudaGetSymbolAddress((void**)&outwh, g_outwh);
    cudaGetSymbolAddress((void**)&w1h,   g_w1h);
    cudaGetSymbolAddress((void**)&w2h,   g_w2h);
    cudaGetSymbolAddress((void**)&attnh, g_attnh);
    cudaGetSymbolAddress((void**)&x1h,   g_x1h);
    cudaGetSymbolAddress((void**)&hh,    g_hh);

    dim3 blk(256);

    // 0) fp16 conversions (weights + src)
    f2h_kernel<<<(NTOK * D_) / 2048, blk>>>(src, srch, NTOK * D_);
    f2h_kernel<<<(D3_ * D_) / 2048, blk>>>(inw, inwh, D3_ * D_);
    f2h_kernel<<<(D_ * D_) / 2048, blk>>>(outw, outwh, D_ * D_);
    f2h_kernel<<<(E_ * F_ * D_) / 2048, blk>>>(w1, w1h, E_ * F_ * D_);
    f2h_kernel<<<(E_ * D_ * F_) / 2048, blk>>>(w2, w2h, E_ * D_ * F_);

    // 1) qkv = src @ in_proj_w^T + b   [8192 x 3072], fp16 out
    gemm_h<false, false, true><<<dim3(D3_ / 128, NTOK / 128), blk>>>(
        srch, D_, inwh, D_, inb, nullptr, qkvh, D3_, NTOK, D3_, D_, 0, 0);

    // 2) attention -> attnh [8192 x 1024] (fp16 in/out)
    attn_h<<<dim3(S_ / 128, B_ * H_), blk>>>(qkvh, attnh);

    // 3) proj = attn @ out_proj_w^T + b [8192 x 1024], fp32 out
    gemm_h<false, false, false><<<dim3(D_ / 128, NTOK / 128), blk>>>(
        attnh, D_, outwh, D_, outb, proj, nullptr, D_, NTOK, D_, D_, 0, 0);

    // 4) x1 = LN(src + proj)  (fp32 + fp16 copies)
    add_ln_kernel<true><<<NTOK, blk>>>(src, proj, g1, be1, x1, x1h);

    // 5) MoE: batched expert GEMMs; h stays fp16
    gemm_h<true, true, true><<<dim3(F_ / 128, 68), blk>>>(
        x1h, D_, w1h, D_, b1, nullptr, hh, F_, NTOK, F_, D_,
        (size_t)F_ * D_, F_);
    gemm_h<false, true, false><<<dim3(D_ / 128, 68), blk>>>(
        hh, F_, w2h, F_, b2, moe, nullptr, D_, NTOK, D_, F_,
        (size_t)D_ * F_, D_);

    // 6) out = LN(x1 + moe)
    add_ln_kernel<false><<<NTOK, blk>>>(x1, moe, g2, be2, out, nullptr);
}

// round 10
// speedup vs baseline: 10.3469x; 1.0687x over previous
#include <cuda_runtime.h>
#include <mma.h>
#include <cuda_fp16.h>
#include <math.h>
#include <cstdint>

using namespace nvcuda;

#define S_  1024
#define B_  8
#define D_  1024
#define H_  16
#define HD_ 64
#define F_  4096
#define E_  8
#define NTOK (S_ * B_)      // 8192 tokens
#define D3_ (3 * D_)        // 3072

// ---------------- scratch (device globals: no allocs allowed) ----------------
__device__ __half g_qkvh [(size_t)NTOK * D3_];
__device__ float  g_proj[(size_t)NTOK * D_];
__device__ float  g_x1  [(size_t)NTOK * D_];
__device__ float  g_moe [(size_t)NTOK * D_];
__device__ __half g_srch [(size_t)NTOK * D_];
__device__ __half g_inwh [(size_t)D3_ * D_];
__device__ __half g_outwh[(size_t)D_ * D_];
__device__ __half g_w1h  [(size_t)E_ * F_ * D_];
__device__ __half g_w2h  [(size_t)E_ * D_ * F_];
__device__ __half g_attnh[(size_t)NTOK * D_];
__device__ __half g_x1h  [(size_t)NTOK * D_];
__device__ __half g_hh   [(size_t)NTOK * F_];

// ---------------------------------------------------------------------------
// PTX helpers
// ---------------------------------------------------------------------------
__device__ __forceinline__ void cp_async16(unsigned int smem_addr,
                                           const void* gptr, bool valid)
{
    int sz = valid ? 16 : 0;
    asm volatile("cp.async.cg.shared.global [%0], [%1], 16, %2;\n"
                 :: "r"(smem_addr), "l"(gptr), "r"(sz));
}
__device__ __forceinline__ void cp_commit() {
    asm volatile("cp.async.commit_group;\n");
}
__device__ __forceinline__ void cp_wait1() {
    asm volatile("cp.async.wait_group 1;\n");
}

// fp16 mma m16n8k16, fp32 accumulate in place
__device__ __forceinline__ void mma_h16(float d[4], const unsigned a[4],
                                        const unsigned b[2])
{
    asm volatile(
        "mma.sync.aligned.m16n8k16.row.col.f32.f16.f16.f32 "
        "{%0,%1,%2,%3}, {%4,%5,%6,%7}, {%8,%9}, {%0,%1,%2,%3};"
        : "+f"(d[0]), "+f"(d[1]), "+f"(d[2]), "+f"(d[3])
        : "r"(a[0]), "r"(a[1]), "r"(a[2]), "r"(a[3]), "r"(b[0]), "r"(b[1]));
}

// ---------------------------------------------------------------------------
// fp32 -> fp16 convert (RN), 8 elements per thread
// ---------------------------------------------------------------------------
__global__ void __launch_bounds__(256)
f2h_kernel(const float* __restrict__ in, __half* __restrict__ out, int n)
{
    int i = (blockIdx.x * 256 + threadIdx.x) * 8;
    if (i >= n) return;
    float4 a = *(const float4*)(in + i);
    float4 b = *(const float4*)(in + i + 4);
    __half2 h0 = __floats2half2_rn(a.x, a.y);
    __half2 h1 = __floats2half2_rn(a.z, a.w);
    __half2 h2 = __floats2half2_rn(b.x, b.y);
    __half2 h3 = __floats2half2_rn(b.z, b.w);
    uint4 u;
    u.x = *(unsigned*)&h0; u.y = *(unsigned*)&h1;
    u.z = *(unsigned*)&h2; u.w = *(unsigned*)&h3;
    *(uint4*)(out + i) = u;
}

// ---------------------------------------------------------------------------
// fp16 WMMA GEMM (m16n16k16), 3-stage cp.async pipeline, fp32 accumulate.
//   C[M,N] = A[M,K] @ W[N,K]^T + bias[N]   (optional ReLU, optional half out)
// Block tile 128x128, BK=32, 256 threads = 8 warps, warp tile 32x64.
// Dynamic smem: 3 stages x (A,B) 128x40 halfs = 61440 bytes.
// ---------------------------------------------------------------------------
#define HBK  32
#define HAST 40   // half stride (32 + 8 pad); 80 bytes/row
#define GST_BYTES (128 * HAST * 2)          // one stage of one matrix: 10240 B
#define GSMEM (6 * GST_BYTES)               // 61440 B

template<bool RELU, bool MOE, bool HOUT>
__global__ void __launch_bounds__(256, 2)
gemm_h(const __half* __restrict__ Abase, int lda,
       const __half* __restrict__ Wbase, int ldb,
       const float* __restrict__ biasbase,
       float* __restrict__ C32, __half* __restrict__ C16, int ldc,
       int M, int N, int K, size_t wstride, int bstride)
{
    extern __shared__ __align__(16) __half dsm[];
    __half* Ah = dsm;                      // 3 stages
    __half* Bh = dsm + 3 * 128 * HAST;     // 3 stages

    const int tid  = threadIdx.x;
    const int warp = tid >> 5;
    const int lane = tid & 31;
    const int wm   = warp & 3;
    const int wn   = warp >> 2;
    const int n0   = blockIdx.x * 128;

    int m0, Mb;
    const __half* A = Abase;
    const __half* W = Wbase;
    const float* bias = biasbase;
    if (MOE) {
        const int tcnt[8] = {54, 7, 2, 1, 1, 1, 1, 1};
        const int toff[8] = {0, 6852, 7709, 7963, 8070, 8125, 8157, 8177};
        const int tn[8]   = {6852, 857, 254, 107, 55, 32, 20, 15};
        int y = blockIdx.y, e = 0, acc = 0;
        while (y >= acc + tcnt[e]) { acc += tcnt[e]; e++; }
        m0 = toff[e] + (y - acc) * 128;
        Mb = toff[e] + tn[e];
        W    = Wbase + (size_t)e * wstride;
        bias = biasbase + (size_t)e * bstride;
    } else {
        m0 = blockIdx.y * 128;
        Mb = M;
    }

    const int lrow = tid >> 2;          // 0..63
    const int lch  = tid & 3;           // 16B chunk: 8 halfs

    unsigned sA = (unsigned)__cvta_generic_to_shared(Ah);
    unsigned sB = (unsigned)__cvta_generic_to_shared(Bh);

    auto issue = [&](int stage, int k0) {
#pragma unroll
        for (int t = 0; t < 2; t++) {
            int row = lrow + t * 64;
            cp_async16(sA + stage * GST_BYTES + (row * HAST + lch * 8) * 2,
                       A + (size_t)(m0 + row) * lda + k0 + lch * 8,
                       m0 + row < Mb);
            cp_async16(sB + stage * GST_BYTES + (row * HAST + lch * 8) * 2,
                       W + (size_t)(n0 + row) * ldb + k0 + lch * 8,
                       n0 + row < N);
        }
    };

    wmma::fragment<wmma::accumulator, 16, 16, 16, float> accf[2][4];
#pragma unroll
    for (int i = 0; i < 2; i++)
#pragma unroll
        for (int j = 0; j < 4; j++)
            wmma::fill_fragment(accf[i][j], 0.0f);

    const int ntiles = K / HBK;     // >= 32 always
    issue(0, 0);
    cp_commit();
    issue(1, HBK);
    cp_commit();

    for (int kt = 0; kt < ntiles; kt++) {
        const int cur = kt % 3;
        cp_wait1();            // stage kt resident (kt+1 may be in flight)
        __syncthreads();       // all warps done with stage (kt-1) = (kt+2)%3
        if (kt + 2 < ntiles)
            issue((kt + 2) % 3, (kt + 2) * HBK);
        cp_commit();

        __half* Ac = Ah + cur * 128 * HAST;
        __half* Bc = Bh + cur * 128 * HAST;
#pragma unroll
        for (int kk = 0; kk < HBK; kk += 16) {
            wmma::fragment<wmma::matrix_a, 16, 16, 16, __half,
                           wmma::row_major> af[2];
            wmma::fragment<wmma::matrix_b, 16, 16, 16, __half,
                           wmma::col_major> bf[4];
#pragma unroll
            for (int i = 0; i < 2; i++)
                wmma::load_matrix_sync(af[i],
                    Ac + (wm * 32 + i * 16) * HAST + kk, HAST);
#pragma unroll
            for (int j = 0; j < 4; j++)
                wmma::load_matrix_sync(bf[j],
                    Bc + (wn * 64 + j * 16) * HAST + kk, HAST);
#pragma unroll
            for (int i = 0; i < 2; i++)
#pragma unroll
                for (int j = 0; j < 4; j++)
                    wmma::mma_sync(accf[i][j], af[i], bf[j], accf[i][j]);
        }
    }

    // epilogue: stage 16x16 fragments through smem; lane owns 8 consecutive cols
    __syncthreads();
    float* sb = (float*)dsm + warp * 256;
    const int er = lane >> 1;            // row 0..15
    const int ec = (lane & 1) * 8;       // col base 0 or 8
#pragma unroll
    for (int i = 0; i < 2; i++) {
#pragma unroll
        for (int j = 0; j < 4; j++) {
            wmma::store_matrix_sync(sb, accf[i][j], 16, wmma::mem_row_major);
            __syncwarp();
            int r = m0 + wm * 32 + i * 16 + er;
            int c = n0 + wn * 64 + j * 16 + ec;
            if (r < Mb) {
                float v[8];
#pragma unroll
                for (int q = 0; q < 8; q++) {
                    v[q] = sb[er * 16 + ec + q] + bias[c + q];
                    if (RELU) v[q] = fmaxf(v[q], 0.f);
                }
                if (HOUT) {
                    __half2 h0 = __floats2half2_rn(v[0], v[1]);
                    __half2 h1 = __floats2half2_rn(v[2], v[3]);
                    __half2 h2 = __floats2half2_rn(v[4], v[5]);
                    __half2 h3 = __floats2half2_rn(v[6], v[7]);
                    uint4 u;
                    u.x = *(unsigned*)&h0; u.y = *(unsigned*)&h1;
                    u.z = *(unsigned*)&h2; u.w = *(unsigned*)&h3;
                    *(uint4*)(C16 + (size_t)r * ldc + c) = u;
                } else {
                    *(float4*)(C32 + (size_t)r * ldc + c) =
                        make_float4(v[0], v[1], v[2], v[3]);
                    *(float4*)(C32 + (size_t)r * ldc + c + 4) =
                        make_float4(v[4], v[5], v[6], v[7]);
                }
            }
            __syncwarp();
        }
    }
}

// ---------------------------------------------------------------------------
// Flash attention, register-resident FA2, fp16 mma.m16n8k16 (unchanged R9).
// ---------------------------------------------------------------------------
#define KST 72   // half stride for K/Vt/P rows

__global__ void __launch_bounds__(256)
attn_h(const __half* __restrict__ qkv, __half* __restrict__ out)
{
    __shared__ __half Ks[64 * KST];          // [key][d]
    __shared__ __half Vt[64 * KST];          // [d][key]
    __shared__ __half Ps[8 * 16 * KST];      // per-warp [row][key]

    const int tid  = threadIdx.x;
    const int warp = tid >> 5, lane = tid & 31;
    const int ra = lane >> 2, q4 = lane & 3;
    const int s0 = blockIdx.x * 128;
    const int b  = blockIdx.y >> 4, h = blockIdx.y & 15;
    __half* Pw = Ps + warp * 16 * KST;

    unsigned qa[4][4];
    {
        const __half2 sc = __half2half2(__float2half(0.125f));
        const int r0 = s0 + warp * 16;
        const __half* rowA = qkv + ((size_t)(r0 + ra) * B_ + b) * D3_ + h * HD_;
        const __half* rowB = qkv + ((size_t)(r0 + ra + 8) * B_ + b) * D3_ + h * HD_;
#pragma unroll
        for (int kk = 0; kk < 4; kk++) {
            __half2 v;
            v = __hmul2(*(const __half2*)(rowA + 16 * kk + 2 * q4), sc);
            qa[kk][0] = *(unsigned*)&v;
            v = __hmul2(*(const __half2*)(rowB + 16 * kk + 2 * q4), sc);
            qa[kk][1] = *(unsigned*)&v;
            v = __hmul2(*(const __half2*)(rowA + 16 * kk + 2 * q4 + 8), sc);
            qa[kk][2] = *(unsigned*)&v;
            v = __hmul2(*(const __half2*)(rowB + 16 * kk + 2 * q4 + 8), sc);
            qa[kk][3] = *(unsigned*)&v;
        }
    }

    float oa[8][4];
#pragma unroll
    for (int j = 0; j < 8; j++)
#pragma unroll
        for (int e = 0; e < 4; e++) oa[j][e] = 0.f;
    float m_a = -1e30f, m_b = -1e30f, l_a = 0.f, l_b = 0.f;

    for (int t0 = 0; t0 < S_; t0 += 64) {
#pragma unroll
        for (int it = 0; it < 2; it++) {
            int i   = tid + it * 256;        // 0..511
            int key = i >> 3;
            int d8  = (i & 7) * 8;
            size_t base = ((size_t)(t0 + key) * B_ + b) * D3_ + h * HD_ + d8;
            *(uint4*)(Ks + key * KST + d8) = *(const uint4*)(qkv + base + D_);
            uint4 vv = *(const uint4*)(qkv + base + 2 * D_);
            const __half* vh = (const __half*)&vv;
#pragma unroll
            for (int q = 0; q < 8; q++)
                Vt[(d8 + q) * KST + key] = vh[q];
        }
        __syncthreads();

        float sacc[8][4];
#pragma unroll
        for (int j = 0; j < 8; j++)
#pragma unroll
            for (int e = 0; e < 4; e++) sacc[j][e] = 0.f;
#pragma unroll
        for (int kk = 0; kk < 4; kk++) {
#pragma unroll
            for (int j = 0; j < 8; j++) {
                unsigned bb[2];
                const __half* kr = Ks + (8 * j + ra) * KST + 16 * kk + 2 * q4;
                bb[0] = *(const unsigned*)(kr);
                bb[1] = *(const unsigned*)(kr + 8);
                mma_h16(sacc[j], qa[kk], bb);
            }
        }

        float mxa = sacc[0][0], mxb = sacc[0][2];
#pragma unroll
        for (int j = 0; j < 8; j++) {
            mxa = fmaxf(mxa, fmaxf(sacc[j][0], sacc[j][1]));
            mxb = fmaxf(mxb, fmaxf(sacc[j][2], sacc[j][3]));
        }
        mxa = fmaxf(mxa, __shfl_xor_sync(0xffffffffu, mxa, 1));
        mxa = fmaxf(mxa, __shfl_xor_sync(0xffffffffu, mxa, 2));
        mxb = fmaxf(mxb, __shfl_xor_sync(0xffffffffu, mxb, 1));
        mxb = fmaxf(mxb, __shfl_xor_sync(0xffffffffu, mxb, 2));

        float mna = fmaxf(m_a, mxa), mnb = fmaxf(m_b, mxb);
        float ca = __expf(m_a - mna), cb = __expf(m_b - mnb);
        m_a = mna; m_b = mnb;

        float sa = 0.f, sb2 = 0.f;
#pragma unroll
        for (int j = 0; j < 8; j++) {
            __half2 pA = __floats2half2_rn(__expf(sacc[j][0] - mna),
                                           __expf(sacc[j][1] - mna));
            __half2 pB = __floats2half2_rn(__expf(sacc[j][2] - mnb),
                                           __expf(sacc[j][3] - mnb));
            float2 fA = __half22float2(pA);
            float2 fB = __half22float2(pB);
            sa  += fA.x + fA.y;
            sb2 += fB.x + fB.y;
            *(__half2*)(Pw + ra * KST + 8 * j + 2 * q4)       = pA;
            *(__half2*)(Pw + (ra + 8) * KST + 8 * j + 2 * q4) = pB;
        }
        sa  += __shfl_xor_sync(0xffffffffu, sa, 1);
        sa  += __shfl_xor_sync(0xffffffffu, sa, 2);
        sb2 += __shfl_xor_sync(0xffffffffu, sb2, 1);
        sb2 += __shfl_xor_sync(0xffffffffu, sb2, 2);
        l_a = l_a * ca + sa;
        l_b = l_b * cb + sb2;

#pragma unroll
        for (int j = 0; j < 8; j++) {
            oa[j][0] *= ca; oa[j][1] *= ca;
            oa[j][2] *= cb; oa[j][3] *= cb;
        }
        __syncwarp();

#pragma unroll
        for (int kk = 0; kk < 4; kk++) {
            unsigned aa[4];
            aa[0] = *(const unsigned*)(Pw + ra * KST + 16 * kk + 2 * q4);
            aa[1] = *(const unsigned*)(Pw + (ra + 8) * KST + 16 * kk + 2 * q4);
            aa[2] = *(const unsigned*)(Pw + ra * KST + 16 * kk + 2 * q4 + 8);
            aa[3] = *(const unsigned*)(Pw + (ra + 8) * KST + 16 * kk + 2 * q4 + 8);
#pragma unroll
            for (int j = 0; j < 8; j++) {
                unsigned bb[2];
                const __half* vr = Vt + (8 * j + ra) * KST + 16 * kk + 2 * q4;
                bb[0] = *(const unsigned*)(vr);
                bb[1] = *(const unsigned*)(vr + 8);
                mma_h16(oa[j], aa, bb);
            }
        }
        __syncthreads();
    }

    {
        float inva = 1.f / l_a, invb = 1.f / l_b;
        const int r0 = s0 + warp * 16;
        __half* dstA = out + ((size_t)(r0 + ra) * B_ + b) * D_ + h * HD_;
        __half* dstB = out + ((size_t)(r0 + ra + 8) * B_ + b) * D_ + h * HD_;
#pragma unroll
        for (int j = 0; j < 8; j++) {
            *(__half2*)(dstA + 8 * j + 2 * q4) =
                __floats2half2_rn(oa[j][0] * inva, oa[j][1] * inva);
            *(__half2*)(dstB + 8 * j + 2 * q4) =
                __floats2half2_rn(oa[j][2] * invb, oa[j][3] * invb);
        }
    }
}

// ---------------------------------------------------------------------------
// out = LayerNorm(a + r) * gamma + beta  — vectorized: 256 thr x 1 float4.
// ---------------------------------------------------------------------------
template<bool HOUT>
__global__ void __launch_bounds__(256)
add_ln_kernel(const float* __restrict__ a, const float* __restrict__ r,
              const float* __restrict__ gamma, const float* __restrict__ beta,
              float* __restrict__ out, __half* __restrict__ outh)
{
    const int row = blockIdx.x;
    const int tid = threadIdx.x;
    __shared__ float ws[8], wq[8];
    __shared__ float red[2];

    const size_t base4 = (size_t)row * 256 + tid;
    float4 va = ((const float4*)a)[base4];
    float4 vr = ((const float4*)r)[base4];
    float4 v = make_float4(va.x + vr.x, va.y + vr.y, va.z + vr.z, va.w + vr.w);

    float s  = v.x + v.y + v.z + v.w;
    float sq = v.x * v.x + v.y * v.y + v.z * v.z + v.w * v.w;
#pragma unroll
    for (int o = 16; o > 0; o >>= 1) {
        s  += __shfl_xor_sync(0xffffffffu, s, o);
        sq += __shfl_xor_sync(0xffffffffu, sq, o);
    }
    int lane = tid & 31, wid = tid >> 5;
    if (lane == 0) { ws[wid] = s; wq[wid] = sq; }
    __syncthreads();
    if (tid == 0) {
        float Ssum = 0.f, Q = 0.f;
#pragma unroll
        for (int w = 0; w < 8; w++) { Ssum += ws[w]; Q += wq[w]; }
        float mu  = Ssum * (1.0f / D_);
        float var = Q * (1.0f / D_) - mu * mu;
        red[0] = mu;
        red[1] = rsqrtf(var + 1e-5f);
    }
    __syncthreads();
    const float mu = red[0], rstd = red[1];

    float4 g  = ((const float4*)gamma)[tid];
    float4 be = ((const float4*)beta)[tid];
    float4 o;
    o.x = (v.x - mu) * rstd * g.x + be.x;
    o.y = (v.y - mu) * rstd * g.y + be.y;
    o.z = (v.z - mu) * rstd * g.z + be.z;
    o.w = (v.w - mu) * rstd * g.w + be.w;
    ((float4*)out)[base4] = o;
    if (HOUT) {
        __half2 h0 = __floats2half2_rn(o.x, o.y);
        __half2 h1 = __floats2half2_rn(o.z, o.w);
        uint2 u;
        u.x = *(unsigned*)&h0;
        u.y = *(unsigned*)&h1;
        ((uint2*)outh)[base4] = u;
    }
}

// ---------------------------------------------------------------------------
extern "C" void kernel_launch(void* const* d_in, const int* in_sizes, int n_in,
                              void* d_out, int out_size)
{
    (void)in_sizes; (void)n_in; (void)out_size;
    const float* src  = (const float*)d_in[0];
    const float* inw  = (const float*)d_in[1];
    const float* inb  = (const float*)d_in[2];
    const float* outw = (const float*)d_in[3];
    const float* outb = (const float*)d_in[4];
    const float* g1   = (const float*)d_in[5];
    const float* be1  = (const float*)d_in[6];
    const float* g2   = (const float*)d_in[7];
    const float* be2  = (const float*)d_in[8];
    const float* w1   = (const float*)d_in[9];
    const float* b1   = (const float*)d_in[10];
    const float* w2   = (const float*)d_in[11];
    const float* b2   = (const float*)d_in[12];
    float* out = (float*)d_out;

    float  *proj, *x1, *moe;
    __half *qkvh, *srch, *inwh, *outwh, *w1h, *w2h, *attnh, *x1h, *hh;
    cudaGetSymbolAddress((void**)&qkvh,  g_qkvh);
    cudaGetSymbolAddress((void**)&proj,  g_proj);
    cudaGetSymbolAddress((void**)&x1,    g_x1);
    cudaGetSymbolAddress((void**)&moe,   g_moe);
    cudaGetSymbolAddress((void**)&srch,  g_srch);
    cudaGetSymbolAddress((void**)&inwh,  g_inwh);
    cudaGetSymbolAddress((void**)&outwh, g_outwh);
    cudaGetSymbolAddress((void**)&w1h,   g_w1h);
    cudaGetSymbolAddress((void**)&w2h,   g_w2h);
    cudaGetSymbolAddress((void**)&attnh, g_attnh);
    cudaGetSymbolAddress((void**)&x1h,   g_x1h);
    cudaGetSymbolAddress((void**)&hh,    g_hh);

    cudaFuncSetAttribute(gemm_h<false, false, true>,
                         cudaFuncAttributeMaxDynamicSharedMemorySize, GSMEM);
    cudaFuncSetAttribute(gemm_h<false, false, false>,
                         cudaFuncAttributeMaxDynamicSharedMemorySize, GSMEM);
    cudaFuncSetAttribute(gemm_h<true, true, true>,
                         cudaFuncAttributeMaxDynamicSharedMemorySize, GSMEM);
    cudaFuncSetAttribute(gemm_h<false, true, false>,
                         cudaFuncAttributeMaxDynamicSharedMemorySize, GSMEM);

    dim3 blk(256);

    // 0) fp16 conversions (weights + src)
    f2h_kernel<<<(NTOK * D_) / 2048, blk>>>(src, srch, NTOK * D_);
    f2h_kernel<<<(D3_ * D_) / 2048, blk>>>(inw, inwh, D3_ * D_);
    f2h_kernel<<<(D_ * D_) / 2048, blk>>>(outw, outwh, D_ * D_);
    f2h_kernel<<<(E_ * F_ * D_) / 2048, blk>>>(w1, w1h, E_ * F_ * D_);
    f2h_kernel<<<(E_ * D_ * F_) / 2048, blk>>>(w2, w2h, E_ * D_ * F_);

    // 1) qkv = src @ in_proj_w^T + b   [8192 x 3072], fp16 out
    gemm_h<false, false, true><<<dim3(D3_ / 128, NTOK / 128), blk, GSMEM>>>(
        srch, D_, inwh, D_, inb, nullptr, qkvh, D3_, NTOK, D3_, D_, 0, 0);

    // 2) attention -> attnh [8192 x 1024] (fp16 in/out)
    attn_h<<<dim3(S_ / 128, B_ * H_), blk>>>(qkvh, attnh);

    // 3) proj = attn @ out_proj_w^T + b [8192 x 1024], fp32 out
    gemm_h<false, false, false><<<dim3(D_ / 128, NTOK / 128), blk, GSMEM>>>(
        attnh, D_, outwh, D_, outb, proj, nullptr, D_, NTOK, D_, D_, 0, 0);

    // 4) x1 = LN(src + proj)  (fp32 + fp16 copies)
    add_ln_kernel<true><<<NTOK, blk>>>(src, proj, g1, be1, x1, x1h);

    // 5) MoE: batched expert GEMMs; h stays fp16
    gemm_h<true, true, true><<<dim3(F_ / 128, 68), blk, GSMEM>>>(
        x1h, D_, w1h, D_, b1, nullptr, hh, F_, NTOK, F_, D_,
        (size_t)F_ * D_, F_);
    gemm_h<false, true, false><<<dim3(D_ / 128, 68), blk, GSMEM>>>(
        hh, F_, w2h, F_, b2, moe, nullptr, D_, NTOK, D_, F_,
        (size_t)D_ * F_, D_);

    // 6) out = LN(x1 + moe)
    add_ln_kernel<false><<<NTOK, blk>>>(x1, moe, g2, be2, out, nullptr);
}